// round 10
// baseline (speedup 1.0000x reference)
#include <cuda_runtime.h>
#include <cuda_fp16.h>
#include <cstdint>

#define DEV __device__ __forceinline__

// ---------------- problem constants ----------------
static constexpr int HID   = 128;
static constexpr int BATCH = 128;
static constexpr int NROWS = 128 * 4096;   // 524288
static constexpr int NT    = NROWS / 128;  // 4096 tiles of 128 rows

// ---------------- SMEM layout (byte offsets) ----------------
static constexpr int OFF_BAR  = 0;                  // stage mbarrier (8B)
static constexpr int OFF_W3   = 64;                 // 64 f32
static constexpr int OFF_B2C  = 320;                // 64 f32
static constexpr int OFF_B3   = 576;                // 1 f32
static constexpr int OFF_CS   = 1024;               // 2 x 128 half2 bias (1KB)
static constexpr int OFF_A1   = 3072;               // 2 x (128 x 256B) f16 swizzled (64KB)
static constexpr int OFF_B1   = OFF_A1 + 65536;     // 256n x 128k f16 swizzled (64KB)
static constexpr int OFF_B2   = OFF_B1 + 65536;     // 64n x 256k f16 swizzled (32KB)
static constexpr int OFF_STG  = OFF_B2 + 32768;     // fp32 stage: 128 x 128 (64KB)
static constexpr int SMEM_BYTES = OFF_STG + 65536;  // 232448 == opt-in max

// named barrier ids: FULL[p]=1+p, EMPTY[p]=3+p, producers-only=5
// ---------------- helpers ----------------
DEV uint32_t s2u(const void* p) {
    uint32_t a;
    asm("{ .reg .u64 t; cvta.to.shared.u64 t, %1; cvt.u32.u64 %0, t; }" : "=r"(a) : "l"(p));
    return a;
}
DEV uint32_t pack2(float a, float b) {
    __half2 h = __floats2half2_rn(a, b);
    return *reinterpret_cast<uint32_t*>(&h);
}
DEV uint32_t hadd2_relu(uint32_t x, uint32_t bias) {
    __half2 v = __hadd2(*reinterpret_cast<__half2*>(&x),
                        *reinterpret_cast<__half2*>(&bias));
    __half2 z = __floats2half2_rn(0.f, 0.f);
    __half2 r = __hmax2(v, z);
    return *reinterpret_cast<uint32_t*>(&r);
}
DEV void mbar_init(uint32_t mbar, uint32_t cnt) {
    asm volatile("mbarrier.init.shared.b64 [%0], %1;" :: "r"(mbar), "r"(cnt) : "memory");
}
DEV void mbar_expect(uint32_t mbar, uint32_t bytes) {
    asm volatile("mbarrier.arrive.expect_tx.shared.b64 _, [%0], %1;" :: "r"(mbar), "r"(bytes) : "memory");
}
DEV void mbar_wait(uint32_t mbar, uint32_t parity) {
    asm volatile(
        "{\n\t.reg .pred P;\n\t"
        "LW%=:\n\t"
        "mbarrier.try_wait.parity.acquire.cta.shared::cta.b64 P, [%0], %1, 0x989680;\n\t"
        "@P bra LD%=;\n\t"
        "bra LW%=;\n\t"
        "LD%=:\n\t}"
        :: "r"(mbar), "r"(parity) : "memory");
}
DEV void bulk_g2s(uint32_t dst, const void* src, uint32_t bytes, uint32_t mbar) {
    asm volatile(
        "cp.async.bulk.shared::cta.global.mbarrier::complete_tx::bytes [%0], [%1], %2, [%3];"
        :: "r"(dst), "l"(src), "r"(bytes), "r"(mbar) : "memory");
}
DEV void ldsm4(uint32_t* r, uint32_t addr) {
    asm volatile("ldmatrix.sync.aligned.m8n8.x4.shared.b16 {%0,%1,%2,%3}, [%4];"
        : "=r"(r[0]), "=r"(r[1]), "=r"(r[2]), "=r"(r[3]) : "r"(addr));
}
DEV void mma16816(float* c, const uint32_t* a, uint32_t b0, uint32_t b1) {
    asm volatile(
        "mma.sync.aligned.m16n8k16.row.col.f32.f16.f16.f32 "
        "{%0,%1,%2,%3}, {%4,%5,%6,%7}, {%8,%9}, {%0,%1,%2,%3};"
        : "+f"(c[0]), "+f"(c[1]), "+f"(c[2]), "+f"(c[3])
        : "r"(a[0]), "r"(a[1]), "r"(a[2]), "r"(a[3]), "r"(b0), "r"(b1));
}
DEV void mma16816h(uint32_t* c, const uint32_t* a, uint32_t b0, uint32_t b1) {
    asm volatile(
        "mma.sync.aligned.m16n8k16.row.col.f16.f16.f16.f16 "
        "{%0,%1}, {%2,%3,%4,%5}, {%6,%7}, {%0,%1};"
        : "+r"(c[0]), "+r"(c[1])
        : "r"(a[0]), "r"(a[1]), "r"(a[2]), "r"(a[3]), "r"(b0), "r"(b1));
}
DEV void bar_sync384(int id) {
    asm volatile("bar.sync %0, 384;" :: "r"(id) : "memory");
}
DEV void bar_arrive384(int id) {
    asm volatile("bar.arrive %0, 384;" :: "r"(id) : "memory");
}
DEV void bar_sync_prod(int id) {
    asm volatile("bar.sync %0, 128;" :: "r"(id) : "memory");
}
DEV void sts128(uint32_t addr, uint32_t a, uint32_t b, uint32_t c, uint32_t d) {
    asm volatile("st.shared.v4.u32 [%0], {%1, %2, %3, %4};"
        :: "r"(addr), "r"(a), "r"(b), "r"(c), "r"(d) : "memory");
}

// ---------------- globals: per-batch bias + single-launch sync flags ----------------
__device__ float g_cbias[BATCH * 256];
__device__ int   g_done   = 0;
__device__ int   g_passed = 0;

// ---------------- main fused kernel (single launch, warp-specialized) ----------------
__global__ void __launch_bounds__(384, 1)
edge_mlp_kernel(const float* __restrict__ nodes,   // [NROWS,128]
                const float* __restrict__ newn,    // [BATCH,128]
                const float* __restrict__ W1,      // [256,256]
                const float* __restrict__ b1,      // [256]
                const float* __restrict__ W2,      // [256,64]
                const float* __restrict__ W3,      // [64]
                const float* __restrict__ b2,      // [64]
                const float* __restrict__ b3,      // [1]
                float* __restrict__ out)           // [NROWS]
{
    extern __shared__ char smem[];
    const uint32_t sb = s2u(smem);
    const int tid  = threadIdx.x;
    const int wid  = tid >> 5;
    const int lane = tid & 31;
    const int l7   = lane & 7;
    const int l3   = lane & 3;
    const int rsel = (lane >> 3) & 1;
    const int usub = lane >> 4;

    float* w3_s = reinterpret_cast<float*>(smem + OFF_W3);
    float* b2_s = reinterpret_cast<float*>(smem + OFF_B2C);
    float* b3_s = reinterpret_cast<float*>(smem + OFF_B3);

    const uint32_t sbar = sb + OFF_BAR;
    const int grid = gridDim.x;
    const int bx = blockIdx.x;

    if (tid == 0) mbar_init(sbar, 1);
    __syncthreads();

    // first tile load issued ASAP (overlaps whole prologue)
    if (tid == 0) {
        mbar_expect(sbar, 65536);
        bulk_g2s(sb + OFF_STG, nodes + (size_t)bx * (128 * HID), 65536, sbar);
    }

    if (tid < 64) { w3_s[tid] = W3[tid]; b2_s[tid] = b2[tid]; }
    if (tid == 0) b3_s[0] = b3[0];

    // producer CTAs compute per-batch bias c[b] = b1 + new[b] @ W1[128:256]
    if (bx < BATCH && tid < 256) {
        const int n = tid;
        float acc = b1[n];
        const float* nb = newn + (size_t)bx * HID;
#pragma unroll 8
        for (int f = 0; f < HID; ++f)
            acc = fmaf(nb[f], W1[(size_t)(HID + f) * 256 + n], acc);
        g_cbias[bx * 256 + n] = acc;
    }
    if (bx < BATCH) {
        __threadfence();
        __syncthreads();
        if (tid == 0) atomicAdd(&g_done, 1);
    }

    // weight conversion: threads 0-255 do B1, threads 256-383 do B2
    if (tid < 256) {
        const int n = tid;
#pragma unroll 4
        for (int kp = 0; kp < 64; ++kp) {
            float a = W1[(size_t)(2 * kp) * 256 + n];
            float b = W1[(size_t)(2 * kp + 1) * 256 + n];
            uint32_t addr = (uint32_t)(n * 256 + (((kp >> 2) ^ (n & 7)) << 4) + (kp & 3) * 4);
            *reinterpret_cast<uint32_t*>(smem + OFF_B1 + addr) = pack2(a, b);
        }
    } else {
        const int pt = tid - 256;   // 0..127
#pragma unroll 4
        for (int j = 0; j < 64; ++j) {
            int idx = pt + j * 128;         // 0..8191
            int n  = idx & 63;
            int kp = idx >> 6;              // 0..127
            float a = W2[(size_t)(2 * kp) * 64 + n];
            float b = W2[(size_t)(2 * kp + 1) * 64 + n];
            uint32_t addr = (uint32_t)(n * 512 + (((kp >> 2) ^ (n & 7)) << 4) + (kp & 3) * 4);
            *reinterpret_cast<uint32_t*>(smem + OFF_B2 + addr) = pack2(a, b);
        }
    }
    __syncthreads();

    // wait for all bias producers, then self-reset flags for graph replay
    if (tid == 0) {
        while (*((volatile int*)&g_done) < BATCH) { }
        if (atomicAdd(&g_passed, 1) == (int)gridDim.x - 1) {
            g_done = 0;
            g_passed = 0;
            __threadfence();
        }
    }
    __syncthreads();

    if (wid < 8) {
        // ================= CONSUMER warps (0-7): pure MMA path =================
        // seed both A1 buffers as EMPTY
        bar_arrive384(3);
        bar_arrive384(4);

        const uint32_t rowOff = (uint32_t)((wid * 16 + l7 + (rsel << 3)) * 256);
        const uint32_t b1LaneBase = sb + OFF_B1 + (uint32_t)((l7 + (rsel << 3)) * 256);
        const uint32_t b2LaneBase = sb + OFF_B2 + (uint32_t)((l7 + (rsel << 3)) * 512);
        const uint32_t soff0 = (uint32_t)((usub ^ l7) << 4);
        const float bias3 = b3_s[0];

        int i = 0;
        for (int t = bx; t < NT; t += grid, ++i) {
            const int p = i & 1;
            bar_sync384(1 + p);                       // wait FULL[p]

            const uint32_t aBase = sb + OFF_A1 + ((uint32_t)p << 15) + rowOff;
            const uint32_t* cs = reinterpret_cast<const uint32_t*>(smem + OFF_CS + p * 512);

            uint32_t areg[8][4];
#pragma unroll
            for (int s = 0; s < 8; ++s)
                ldsm4(areg[s], aBase + (uint32_t)((((s << 1) + usub) ^ l7) << 4));

            float c2[8][4];
#pragma unroll
            for (int f = 0; f < 8; ++f)
#pragma unroll
                for (int q = 0; q < 4; ++q) c2[f][q] = 0.f;

            uint32_t brA[4], brB[4];
            ldsm4(brA, b1LaneBase + soff0);
            ldsm4(brB, b1LaneBase + 4096 + soff0);

            for (int pp = 0; pp < 8; ++pp) {
                const int p0 = 2 * pp;
                const uint32_t bB0 = b1LaneBase + (uint32_t)(p0 * 4096);

                uint32_t c1[2][4];
#pragma unroll
                for (int pb = 0; pb < 2; ++pb)
#pragma unroll
                    for (int q = 0; q < 4; ++q) c1[pb][q] = 0u;

                // layer 1: 8 k-steps, both 16-col streams; B prefetch 1 step deep
#pragma unroll
                for (int s = 0; s < 8; ++s) {
                    const uint32_t nxt = (s < 7)
                        ? (uint32_t)(((((s + 1) << 1) + usub) ^ l7) << 4)
                        : 8192u + soff0;     // s=0 of next pp (pp=7: dummy read in B2 region)
                    uint32_t nA[4], nB[4];
                    ldsm4(nA, bB0 + nxt);
                    mma16816h(&c1[0][0], areg[s], brA[0], brA[2]);
                    mma16816h(&c1[0][2], areg[s], brA[1], brA[3]);
                    ldsm4(nB, bB0 + 4096 + nxt);
                    mma16816h(&c1[1][0], areg[s], brB[0], brB[2]);
                    mma16816h(&c1[1][2], areg[s], brB[1], brB[3]);
                    brA[0] = nA[0]; brA[1] = nA[1]; brA[2] = nA[2]; brA[3] = nA[3];
                    brB[0] = nB[0]; brB[1] = nB[1]; brB[2] = nB[2]; brB[3] = nB[3];
                }

                const uint32_t koffA = (uint32_t)((((p0 << 1) + usub) ^ l7) << 4);
                const uint32_t koffB = (uint32_t)(((((p0 + 1) << 1) + usub) ^ l7) << 4);

                uint32_t rA0[4], rA1[4], rA2[4], rA3[4];
                uint32_t rB0[4], rB1[4], rB2[4], rB3[4];
                ldsm4(rA0, b2LaneBase + koffA);
                ldsm4(rA1, b2LaneBase + 8192 + koffA);

                // epilogue-1: in-place half2 bias + relu; c1 IS the layer-2 A fragment
                {
                    const int cbase = p0 * 8;
                    const uint32_t bv0 = cs[cbase + l3];
                    const uint32_t bv1 = cs[cbase + 4 + l3];
                    c1[0][0] = hadd2_relu(c1[0][0], bv0);
                    c1[0][1] = hadd2_relu(c1[0][1], bv0);
                    c1[0][2] = hadd2_relu(c1[0][2], bv1);
                    c1[0][3] = hadd2_relu(c1[0][3], bv1);
                    const uint32_t bv2 = cs[cbase + 8 + l3];
                    const uint32_t bv3 = cs[cbase + 12 + l3];
                    c1[1][0] = hadd2_relu(c1[1][0], bv2);
                    c1[1][1] = hadd2_relu(c1[1][1], bv2);
                    c1[1][2] = hadd2_relu(c1[1][2], bv3);
                    c1[1][3] = hadd2_relu(c1[1][3], bv3);
                }

                ldsm4(rA2, b2LaneBase + 16384 + koffA);
                ldsm4(rA3, b2LaneBase + 24576 + koffA);

                // layer 2: all A-stream (k=p0) then all B-stream (k=p0+1):
                // per-accumulator order identical to previous rounds (A then B)
                mma16816(c2[0], c1[0], rA0[0], rA0[2]);
                mma16816(c2[1], c1[0], rA0[1], rA0[3]);
                ldsm4(rB0, b2LaneBase + koffB);
                mma16816(c2[2], c1[0], rA1[0], rA1[2]);
                mma16816(c2[3], c1[0], rA1[1], rA1[3]);
                ldsm4(rB1, b2LaneBase + 8192 + koffB);
                mma16816(c2[4], c1[0], rA2[0], rA2[2]);
                mma16816(c2[5], c1[0], rA2[1], rA2[3]);
                ldsm4(rB2, b2LaneBase + 16384 + koffB);
                mma16816(c2[6], c1[0], rA3[0], rA3[2]);
                mma16816(c2[7], c1[0], rA3[1], rA3[3]);
                ldsm4(rB3, b2LaneBase + 24576 + koffB);
                mma16816(c2[0], c1[1], rB0[0], rB0[2]);
                mma16816(c2[1], c1[1], rB0[1], rB0[3]);
                mma16816(c2[2], c1[1], rB1[0], rB1[2]);
                mma16816(c2[3], c1[1], rB1[1], rB1[3]);
                mma16816(c2[4], c1[1], rB2[0], rB2[2]);
                mma16816(c2[5], c1[1], rB2[1], rB2[3]);
                mma16816(c2[6], c1[1], rB3[0], rB3[2]);
                mma16816(c2[7], c1[1], rB3[1], rB3[3]);
            }

            bar_arrive384(3 + p);                     // release EMPTY[p]

            // ---- epilogue 2: relu(C2 + b2) . W3 + b3 -> sigmoid -> out ----
            {
                float accl = 0.f, acch = 0.f;
#pragma unroll
                for (int f2 = 0; f2 < 8; ++f2) {
                    const int col = f2 * 8 + l3 * 2;
                    float w0 = w3_s[col], w1 = w3_s[col + 1];
                    float bb0 = b2_s[col], bb1 = b2_s[col + 1];
                    accl = fmaf(fmaxf(c2[f2][0] + bb0, 0.f), w0, accl);
                    accl = fmaf(fmaxf(c2[f2][1] + bb1, 0.f), w1, accl);
                    acch = fmaf(fmaxf(c2[f2][2] + bb0, 0.f), w0, acch);
                    acch = fmaf(fmaxf(c2[f2][3] + bb1, 0.f), w1, acch);
                }
                accl += __shfl_xor_sync(0xffffffffu, accl, 1);
                accl += __shfl_xor_sync(0xffffffffu, accl, 2);
                acch += __shfl_xor_sync(0xffffffffu, acch, 1);
                acch += __shfl_xor_sync(0xffffffffu, acch, 2);
                if (l3 == 0) {
                    const int row = t * 128 + wid * 16 + (lane >> 2);
                    out[row]     = 1.f / (1.f + __expf(-(accl + bias3)));
                    out[row + 8] = 1.f / (1.f + __expf(-(acch + bias3)));
                }
            }
        }
    } else {
        // ================= PRODUCER warps (8-11): stage -> A1 + bias =================
        const int ptid  = tid - 256;        // 0..127
        const int pw    = ptid >> 5;        // producer warp 0..3
        const int plane = ptid & 31;
        const float4* stg4 = reinterpret_cast<const float4*>(smem + OFF_STG);

        int i = 0;
        for (int t = bx; t < NT; t += grid, ++i) {
            const int p = i & 1;
            // bias prefetch (LDG latency hidden under barrier/mbar waits)
            const int b = t >> 5;           // 32 tiles per batch
            const float2 cb = *reinterpret_cast<const float2*>(&g_cbias[b * 256 + 2 * ptid]);

            bar_sync384(3 + p);                       // wait EMPTY[p]
            mbar_wait(sbar, (uint32_t)(i & 1));       // wait stage load i

            reinterpret_cast<uint32_t*>(smem + OFF_CS + p * 512)[ptid] = pack2(cb.x, cb.y);

            // convert own 32 rows fp32 -> f16 swizzled into A1[p]
            const uint32_t a1p = sb + OFF_A1 + ((uint32_t)p << 15);
#pragma unroll 4
            for (int j = 0; j < 16; ++j) {
                int idx  = plane + j * 32;           // 0..511
                int mloc = idx >> 4;                 // 0..31
                int u    = idx & 15;
                int m    = pw * 32 + mloc;
                float4 v0 = stg4[m * 32 + 2 * u];
                float4 v1 = stg4[m * 32 + 2 * u + 1];
                sts128(a1p + (uint32_t)(m * 256 + ((u ^ (m & 7)) << 4)),
                       pack2(v0.x, v0.y), pack2(v0.z, v0.w),
                       pack2(v1.x, v1.y), pack2(v1.z, v1.w));
            }

            bar_sync_prod(5);                         // all producers done reading stage
            if (ptid == 0 && t + grid < NT) {
                mbar_expect(sbar, 65536);
                bulk_g2s(sb + OFF_STG, nodes + (size_t)(t + grid) * (128 * HID), 65536, sbar);
            }
            bar_arrive384(1 + p);                     // signal FULL[p]
        }
    }
}

// ---------------- launch ----------------
extern "C" void kernel_launch(void* const* d_in, const int* in_sizes, int n_in,
                              void* d_out, int out_size) {
    const float* nodes = (const float*)d_in[0];   // [128,4096,128]
    const float* newn  = (const float*)d_in[1];   // [128,1,128]
    const float* W1    = (const float*)d_in[2];   // [256,256]
    const float* b1    = (const float*)d_in[3];   // [256]
    const float* W2    = (const float*)d_in[4];   // [256,64]
    const float* b2    = (const float*)d_in[5];   // [64]
    const float* W3    = (const float*)d_in[6];   // [64,1]
    const float* b3    = (const float*)d_in[7];   // [1]
    float* out = (float*)d_out;

    (void)in_sizes; (void)n_in; (void)out_size;

    cudaFuncSetAttribute(edge_mlp_kernel,
                         cudaFuncAttributeMaxDynamicSharedMemorySize, SMEM_BYTES);

    int nsm = 148;
    cudaDeviceGetAttribute(&nsm, cudaDevAttrMultiProcessorCount, 0);
    if (nsm <= 0) nsm = 148;
    if (nsm > NT) nsm = NT;

    edge_mlp_kernel<<<nsm, 384, SMEM_BYTES>>>(nodes, newn, W1, b1, W2, W3, b2, b3, out);
}

// round 12
// speedup vs baseline: 1.0413x; 1.0413x over previous
#include <cuda_runtime.h>
#include <cuda_fp16.h>
#include <cstdint>

#define DEV __device__ __forceinline__

// ---------------- problem constants ----------------
static constexpr int HID   = 128;
static constexpr int BATCH = 128;
static constexpr int NROWS = 128 * 4096;   // 524288
static constexpr int NT2   = NROWS / 256;  // 2048 supertiles of 256 rows

// ---------------- SMEM layout (byte offsets) ----------------
static constexpr int OFF_W3   = 64;                 // 64 f32
static constexpr int OFF_B2C  = 320;                // 64 f32
static constexpr int OFF_B3   = 576;                // 1 f32
static constexpr int OFF_CS   = 1024;               // [2 grp][2 ph][128] half2 (2KB)
static constexpr int OFF_A1   = 3072;               // 4 x (128 rows x 256B) f16 swizzled (128KB)
static constexpr int OFF_B1   = OFF_A1 + 131072;    // 256n x 128k f16 swizzled (64KB)
static constexpr int OFF_B2   = OFF_B1 + 65536;     // 64n x 256k f16 swizzled (32KB)
static constexpr int SMEM_BYTES = OFF_B2 + 32768;   // 232448 == opt-in max

// ---------------- helpers ----------------
DEV uint32_t s2u(const void* p) {
    uint32_t a;
    asm("{ .reg .u64 t; cvta.to.shared.u64 t, %1; cvt.u32.u64 %0, t; }" : "=r"(a) : "l"(p));
    return a;
}
DEV uint32_t pack2(float a, float b) {
    __half2 h = __floats2half2_rn(a, b);
    return *reinterpret_cast<uint32_t*>(&h);
}
DEV uint32_t hadd2_relu(uint32_t x, uint32_t bias) {
    __half2 v = __hadd2(*reinterpret_cast<__half2*>(&x),
                        *reinterpret_cast<__half2*>(&bias));
    __half2 z = __floats2half2_rn(0.f, 0.f);
    __half2 r = __hmax2(v, z);
    return *reinterpret_cast<uint32_t*>(&r);
}
DEV void ldsm4(uint32_t* r, uint32_t addr) {
    asm volatile("ldmatrix.sync.aligned.m8n8.x4.shared.b16 {%0,%1,%2,%3}, [%4];"
        : "=r"(r[0]), "=r"(r[1]), "=r"(r[2]), "=r"(r[3]) : "r"(addr));
}
DEV void mma16816(float* c, const uint32_t* a, uint32_t b0, uint32_t b1) {
    asm volatile(
        "mma.sync.aligned.m16n8k16.row.col.f32.f16.f16.f32 "
        "{%0,%1,%2,%3}, {%4,%5,%6,%7}, {%8,%9}, {%0,%1,%2,%3};"
        : "+f"(c[0]), "+f"(c[1]), "+f"(c[2]), "+f"(c[3])
        : "r"(a[0]), "r"(a[1]), "r"(a[2]), "r"(a[3]), "r"(b0), "r"(b1));
}
DEV void mma16816h(uint32_t* c, const uint32_t* a, uint32_t b0, uint32_t b1) {
    asm volatile(
        "mma.sync.aligned.m16n8k16.row.col.f16.f16.f16.f16 "
        "{%0,%1}, {%2,%3,%4,%5}, {%6,%7}, {%0,%1};"
        : "+r"(c[0]), "+r"(c[1])
        : "r"(a[0]), "r"(a[1]), "r"(a[2]), "r"(a[3]), "r"(b0), "r"(b1));
}
DEV void named_bar(int id) {
    asm volatile("bar.sync %0, 128;" :: "r"(id) : "memory");
}
DEV void sts128(uint32_t addr, uint32_t a, uint32_t b, uint32_t c, uint32_t d) {
    asm volatile("st.shared.v4.u32 [%0], {%1, %2, %3, %4};"
        :: "r"(addr), "r"(a), "r"(b), "r"(c), "r"(d) : "memory");
}

// ---------------- globals: per-batch bias + single-launch sync flags ----------------
__device__ float g_cbias[BATCH * 256];
__device__ int   g_done   = 0;
__device__ int   g_passed = 0;

// ---------------- main fused kernel (single launch) ----------------
__global__ void __launch_bounds__(256, 1)
edge_mlp_kernel(const float* __restrict__ nodes,   // [NROWS,128]
                const float* __restrict__ newn,    // [BATCH,128]
                const float* __restrict__ W1,      // [256,256]
                const float* __restrict__ b1,      // [256]
                const float* __restrict__ W2,      // [256,64]
                const float* __restrict__ W3,      // [64]
                const float* __restrict__ b2,      // [64]
                const float* __restrict__ b3,      // [1]
                float* __restrict__ out)           // [NROWS]
{
    extern __shared__ char smem[];
    const uint32_t sb = s2u(smem);
    const int tid  = threadIdx.x;
    const int wid  = tid >> 5;
    const int lane = tid & 31;
    const int l7   = lane & 7;
    const int l3   = lane & 3;
    const int rsel = (lane >> 3) & 1;
    const int usub = lane >> 4;
    const int g    = wid >> 2;          // group 0: warps 0-3; group 1: warps 4-7
    const int gwid = wid & 3;           // warp within group

    float* w3_s = reinterpret_cast<float*>(smem + OFF_W3);
    float* b2_s = reinterpret_cast<float*>(smem + OFF_B2C);
    float* b3_s = reinterpret_cast<float*>(smem + OFF_B3);

    const int grid = gridDim.x;
    const int bx = blockIdx.x;

    // small constants
    if (tid < 64) { w3_s[tid] = W3[tid]; b2_s[tid] = b2[tid]; }
    if (tid == 0) b3_s[0] = b3[0];

    // producer CTAs compute per-batch bias c[b] = b1 + new[b] @ W1[128:256]
    if (bx < BATCH) {
        const int n = tid;
        float acc = b1[n];
        const float* nb = newn + (size_t)bx * HID;
#pragma unroll 8
        for (int f = 0; f < HID; ++f)
            acc = fmaf(nb[f], W1[(size_t)(HID + f) * 256 + n], acc);
        g_cbias[bx * 256 + n] = acc;
        __threadfence();
        __syncthreads();
        if (tid == 0) atomicAdd(&g_done, 1);
    }

    // B1: [n=256][k=128] f16, 256B rows, XOR swizzle. B1[n][k]=W1[k*256+n]
    {
        const int n = tid;
#pragma unroll 4
        for (int kp = 0; kp < 64; ++kp) {
            float a = W1[(size_t)(2 * kp) * 256 + n];
            float b = W1[(size_t)(2 * kp + 1) * 256 + n];
            uint32_t addr = (uint32_t)(n * 256 + (((kp >> 2) ^ (n & 7)) << 4) + (kp & 3) * 4);
            *reinterpret_cast<uint32_t*>(smem + OFF_B1 + addr) = pack2(a, b);
        }
    }
    // B2: [n=64][k=256] f16, 512B rows, same swizzle. B2[n][k]=W2[k*64+n]
    {
#pragma unroll 4
        for (int j = 0; j < 32; ++j) {
            int idx = tid + j * 256;
            int n  = idx & 63;
            int kp = idx >> 6;
            float a = W2[(size_t)(2 * kp) * 64 + n];
            float b = W2[(size_t)(2 * kp + 1) * 64 + n];
            uint32_t addr = (uint32_t)(n * 512 + (((kp >> 2) ^ (n & 7)) << 4) + (kp & 3) * 4);
            *reinterpret_cast<uint32_t*>(smem + OFF_B2 + addr) = pack2(a, b);
        }
    }
    __syncthreads();

    // wait for all bias producers; self-reset flags for graph replay
    if (tid == 0) {
        while (*((volatile int*)&g_done) < BATCH) { }
        if (atomicAdd(&g_passed, 1) == (int)gridDim.x - 1) {
            g_done = 0;
            g_passed = 0;
            __threadfence();
        }
    }
    __syncthreads();
    // after this point: the two groups run decoupled (per-group named barriers only)

    // per-warp bases
    const uint32_t rowOff = (uint32_t)((gwid * 32 + l7 + (rsel << 3)) * 256);
    const uint32_t b1LaneBase = sb + OFF_B1 + (uint32_t)((l7 + (rsel << 3)) * 256);
    const uint32_t b2LaneBase = sb + OFF_B2 + (uint32_t)((l7 + (rsel << 3)) * 512);
    const uint32_t soff0 = (uint32_t)((usub ^ l7) << 4);
    const int cidx = gwid * 32 + lane;           // 0..127 within group
    const float bias3 = b3_s[0];
    uint32_t* cs_base = reinterpret_cast<uint32_t*>(smem + OFF_CS);

    // ---- prologue: convert tile 0 (phase 0) directly global -> f16 A1 ----
    {
        const int t0 = bx;
        const float4* g4 = reinterpret_cast<const float4*>(nodes)
                           + ((size_t)t0 * 256 + g * 128 + gwid * 32) * 32;
        const uint32_t a1p = sb + OFF_A1 + ((uint32_t)(g * 2 + 0) << 15);
#pragma unroll 4
        for (int j = 0; j < 16; ++j) {
            int idx  = lane + j * 32;
            int mloc = idx >> 4;
            int u    = idx & 15;
            float4 v0 = g4[mloc * 32 + 2 * u];
            float4 v1 = g4[mloc * 32 + 2 * u + 1];
            int m = gwid * 32 + mloc;
            sts128(a1p + (uint32_t)(m * 256 + ((u ^ (m & 7)) << 4)),
                   pack2(v0.x, v0.y), pack2(v0.z, v0.w),
                   pack2(v1.x, v1.y), pack2(v1.z, v1.w));
        }
        const int b0i = t0 >> 4;
        const float2 cb = *reinterpret_cast<const float2*>(&g_cbias[b0i * 256 + 2 * cidx]);
        cs_base[(g * 2 + 0) * 128 + cidx] = pack2(cb.x, cb.y);
    }
    named_bar(1 + g);   // A1[ph=0] + cs[ph=0] for this group ready

    int k = 0;
    for (int t = bx; t < NT2; t += grid, ++k) {
        const int ph = k & 1;
        const int tn = t + grid;
        const bool has_next = (tn < NT2);

        // next-tile bias prefetch (hides LDG latency under areg/MMA work)
        float2 cbn = make_float2(0.f, 0.f);
        if (has_next) {
            const int bn = tn >> 4;
            cbn = *reinterpret_cast<const float2*>(&g_cbias[bn * 256 + 2 * cidx]);
        }

        const uint32_t aBase = sb + OFF_A1 + ((uint32_t)(g * 2 + ph) << 15) + rowOff;
        const uint32_t a1n   = sb + OFF_A1 + ((uint32_t)(g * 2 + (ph ^ 1)) << 15);
        const uint32_t* cs   = cs_base + (g * 2 + ph) * 128;

        // convert-source pointer for next tile (this warp's 32 rows)
        const float4* gsrc4 = reinterpret_cast<const float4*>(nodes)
                              + ((size_t)tn * 256 + g * 128 + gwid * 32) * 32;

        // ---- load A fragments for current tile: 2 row-halves x 8 k-steps ----
        uint32_t areg[2][8][4];
#pragma unroll
        for (int s = 0; s < 8; ++s) {
            ldsm4(areg[0][s], aBase + (uint32_t)((((s << 1) + usub) ^ l7) << 4));
            ldsm4(areg[1][s], aBase + 4096u + (uint32_t)((((s << 1) + usub) ^ l7) << 4));
        }

        float c2[2][8][4];
#pragma unroll
        for (int h = 0; h < 2; ++h)
#pragma unroll
            for (int f = 0; f < 8; ++f)
#pragma unroll
                for (int q = 0; q < 4; ++q) c2[h][f][q] = 0.f;

        // convert pipeline: preload j=0,1 of next tile
        float4 cv0[2], cv1[2];
        if (has_next) {
#pragma unroll
            for (int jj = 0; jj < 2; ++jj) {
                int idx  = lane + jj * 32;
                int mloc = idx >> 4;
                int u    = idx & 15;
                cv0[jj] = gsrc4[mloc * 32 + 2 * u];
                cv1[jj] = gsrc4[mloc * 32 + 2 * u + 1];
            }
        }

        uint32_t brc0[4];
        ldsm4(brc0, b1LaneBase + soff0);   // pp=0, s=0 (stream 0)

        for (int pp = 0; pp < 8; ++pp) {
            const int p0 = 2 * pp;
            // c1[stream][row-half][4] — f16 accum, doubles as layer-2 A fragment
            uint32_t c1[2][2][4];
#pragma unroll
            for (int pb = 0; pb < 2; ++pb)
#pragma unroll
                for (int h = 0; h < 2; ++h)
#pragma unroll
                    for (int q = 0; q < 4; ++q) c1[pb][h][q] = 0u;

            const uint32_t bB0 = b1LaneBase + (uint32_t)(p0 * 4096);

            // ---- layer 1: 8 k-steps, both streams x both row-halves (8 MMA/step) ----
#pragma unroll
            for (int s = 0; s < 8; ++s) {
                const uint32_t soff = (uint32_t)((((s << 1) + usub) ^ l7) << 4);
                uint32_t br1[4];
                ldsm4(br1, bB0 + 4096 + soff);
                mma16816h(&c1[0][0][0], areg[0][s], brc0[0], brc0[2]);
                mma16816h(&c1[0][0][2], areg[0][s], brc0[1], brc0[3]);
                mma16816h(&c1[0][1][0], areg[1][s], brc0[0], brc0[2]);
                mma16816h(&c1[0][1][2], areg[1][s], brc0[1], brc0[3]);
                uint32_t brn0[4];
                ldsm4(brn0, (s < 7)
                        ? bB0 + (uint32_t)(((((s + 1) << 1) + usub) ^ l7) << 4)
                        : bB0 + 8192 + soff0);   // s=0 of next pp (pp=7: dummy in B2 region)
                mma16816h(&c1[1][0][0], areg[0][s], br1[0], br1[2]);
                mma16816h(&c1[1][0][2], areg[0][s], br1[1], br1[3]);
                mma16816h(&c1[1][1][0], areg[1][s], br1[0], br1[2]);
                mma16816h(&c1[1][1][2], areg[1][s], br1[1], br1[3]);
                brc0[0] = brn0[0]; brc0[1] = brn0[1]; brc0[2] = brn0[2]; brc0[3] = brn0[3];
            }

            // ---- interleaved convert: 2 steps of next tile's A (this warp's rows) ----
            if (has_next) {
#pragma unroll
                for (int jj = 0; jj < 2; ++jj) {
                    const int j = 2 * pp + jj;
                    int idx  = lane + j * 32;
                    int mloc = idx >> 4;
                    int u    = idx & 15;
                    int m    = gwid * 32 + mloc;
                    sts128(a1n + (uint32_t)(m * 256 + ((u ^ (m & 7)) << 4)),
                           pack2(cv0[jj].x, cv0[jj].y), pack2(cv0[jj].z, cv0[jj].w),
                           pack2(cv1[jj].x, cv1[jj].y), pack2(cv1[jj].z, cv1[jj].w));
                    if (j + 2 < 16) {
                        int idx2  = lane + (j + 2) * 32;
                        int mloc2 = idx2 >> 4;
                        int u2    = idx2 & 15;
                        cv0[jj] = gsrc4[mloc2 * 32 + 2 * u2];
                        cv1[jj] = gsrc4[mloc2 * 32 + 2 * u2 + 1];
                    }
                }
            }

            const uint32_t koffA = (uint32_t)((((p0 << 1) + usub) ^ l7) << 4);
            const uint32_t koffB = (uint32_t)(((((p0 + 1) << 1) + usub) ^ l7) << 4);

            uint32_t br2a[4];
            ldsm4(br2a, b2LaneBase + koffA);

            // epilogue-1: in-place half2 bias + relu; c1 IS the layer-2 A fragment
#pragma unroll
            for (int pb = 0; pb < 2; ++pb) {
                const int cbase = p0 * 8;
                const uint32_t bvlo = cs[cbase + pb * 8 + l3];
                const uint32_t bvhi = cs[cbase + pb * 8 + 4 + l3];
#pragma unroll
                for (int h = 0; h < 2; ++h) {
                    c1[pb][h][0] = hadd2_relu(c1[pb][h][0], bvlo);
                    c1[pb][h][1] = hadd2_relu(c1[pb][h][1], bvlo);
                    c1[pb][h][2] = hadd2_relu(c1[pb][h][2], bvhi);
                    c1[pb][h][3] = hadd2_relu(c1[pb][h][3], bvhi);
                }
            }

            // ---- layer 2: k-steps p0 (stream A) then p0+1 (stream B); 1-deep prefetch ----
#pragma unroll
            for (int p2 = 0; p2 < 4; ++p2) {
                const uint32_t rowB = (uint32_t)(p2 * 8192);
                uint32_t br2b[4];
                ldsm4(br2b, b2LaneBase + rowB + koffB);
                uint32_t br2an[4];
                if (p2 < 3)
                    ldsm4(br2an, b2LaneBase + (uint32_t)((p2 + 1) * 8192) + koffA);
                // stream A (k = p0): c1[0][h]
                mma16816(c2[0][2 * p2],     c1[0][0], br2a[0], br2a[2]);
                mma16816(c2[0][2 * p2 + 1], c1[0][0], br2a[1], br2a[3]);
                mma16816(c2[1][2 * p2],     c1[0][1], br2a[0], br2a[2]);
                mma16816(c2[1][2 * p2 + 1], c1[0][1], br2a[1], br2a[3]);
                // stream B (k = p0+1): c1[1][h]
                mma16816(c2[0][2 * p2],     c1[1][0], br2b[0], br2b[2]);
                mma16816(c2[0][2 * p2 + 1], c1[1][0], br2b[1], br2b[3]);
                mma16816(c2[1][2 * p2],     c1[1][1], br2b[0], br2b[2]);
                mma16816(c2[1][2 * p2 + 1], c1[1][1], br2b[1], br2b[3]);
                if (p2 < 3) {
                    br2a[0] = br2an[0]; br2a[1] = br2an[1]; br2a[2] = br2an[2]; br2a[3] = br2an[3];
                }
            }
        }

        // store next-tile bias into the other phase buffer
        if (has_next)
            cs_base[(g * 2 + (ph ^ 1)) * 128 + cidx] = pack2(cbn.x, cbn.y);

        // ---- epilogue 2: relu(C2 + b2) . W3 + b3 -> sigmoid -> out ----
#pragma unroll
        for (int h = 0; h < 2; ++h) {
            float accl = 0.f, acch = 0.f;
#pragma unroll
            for (int f2 = 0; f2 < 8; ++f2) {
                const int col = f2 * 8 + l3 * 2;
                float w0 = w3_s[col], w1 = w3_s[col + 1];
                float bb0 = b2_s[col], bb1 = b2_s[col + 1];
                accl = fmaf(fmaxf(c2[h][f2][0] + bb0, 0.f), w0, accl);
                accl = fmaf(fmaxf(c2[h][f2][1] + bb1, 0.f), w1, accl);
                acch = fmaf(fmaxf(c2[h][f2][2] + bb0, 0.f), w0, acch);
                acch = fmaf(fmaxf(c2[h][f2][3] + bb1, 0.f), w1, acch);
            }
            accl += __shfl_xor_sync(0xffffffffu, accl, 1);
            accl += __shfl_xor_sync(0xffffffffu, accl, 2);
            acch += __shfl_xor_sync(0xffffffffu, acch, 1);
            acch += __shfl_xor_sync(0xffffffffu, acch, 2);
            if (l3 == 0) {
                const int row = t * 256 + wid * 32 + 16 * h + (lane >> 2);
                out[row]     = 1.f / (1.f + __expf(-(accl + bias3)));
                out[row + 8] = 1.f / (1.f + __expf(-(acch + bias3)));
            }
        }

        named_bar(1 + g);   // A1[ph^1] + cs[ph^1] published for the group's next tile
    }
}

// ---------------- launch ----------------
extern "C" void kernel_launch(void* const* d_in, const int* in_sizes, int n_in,
                              void* d_out, int out_size) {
    const float* nodes = (const float*)d_in[0];   // [128,4096,128]
    const float* newn  = (const float*)d_in[1];   // [128,1,128]
    const float* W1    = (const float*)d_in[2];   // [256,256]
    const float* b1    = (const float*)d_in[3];   // [256]
    const float* W2    = (const float*)d_in[4];   // [256,64]
    const float* b2    = (const float*)d_in[5];   // [64]
    const float* W3    = (const float*)d_in[6];   // [64,1]
    const float* b3    = (const float*)d_in[7];   // [1]
    float* out = (float*)d_out;

    (void)in_sizes; (void)n_in; (void)out_size;

    cudaFuncSetAttribute(edge_mlp_kernel,
                         cudaFuncAttributeMaxDynamicSharedMemorySize, SMEM_BYTES);

    int nsm = 148;
    cudaDeviceGetAttribute(&nsm, cudaDevAttrMultiProcessorCount, 0);
    if (nsm <= 0) nsm = 148;
    if (nsm > NT2) nsm = NT2;

    edge_mlp_kernel<<<nsm, 256, SMEM_BYTES>>>(nodes, newn, W1, b1, W2, W3, b2, b3, out);
}

// round 14
// speedup vs baseline: 1.0630x; 1.0209x over previous
#include <cuda_runtime.h>
#include <cuda_fp16.h>
#include <cstdint>

#define DEV __device__ __forceinline__

// ---------------- problem constants ----------------
static constexpr int HID    = 128;
static constexpr int BATCH  = 128;
static constexpr int NROWS  = 128 * 4096;     // 524288
static constexpr int NT2    = NROWS / 256;    // 2048 tiles of 256 rows

// ---------------- SMEM layout (byte offsets) ----------------
static constexpr int OFF_BAR  = 0;                  // mbarrier (8B)
static constexpr int OFF_W3   = 64;                 // 64 f32
static constexpr int OFF_B2C  = 320;                // 64 f32
static constexpr int OFF_B3   = 576;                // 1 f32
static constexpr int OFF_CS   = 1024;               // [2][128] half2 bias (1KB)
static constexpr int OFF_A1   = 3072;               // 256 x 128 f16 swizzled (64KB)
static constexpr int OFF_B1   = OFF_A1 + 65536;     // 256n x 128k f16 swizzled (64KB)
static constexpr int OFF_B2   = OFF_B1 + 65536;     // 64n x 256k f16 swizzled (32KB)
static constexpr int OFF_STG  = OFF_B2 + 32768;     // fp32 stage: 128 rows x 128 (64KB)
static constexpr int SMEM_BYTES = OFF_STG + 65536;  // 232448 == opt-in max

// ---------------- helpers ----------------
DEV uint32_t s2u(const void* p) {
    uint32_t a;
    asm("{ .reg .u64 t; cvta.to.shared.u64 t, %1; cvt.u32.u64 %0, t; }" : "=r"(a) : "l"(p));
    return a;
}
DEV uint32_t pack2(float a, float b) {
    __half2 h = __floats2half2_rn(a, b);
    return *reinterpret_cast<uint32_t*>(&h);
}
DEV uint32_t hadd2_relu(uint32_t x, uint32_t bias) {
    __half2 v = __hadd2(*reinterpret_cast<__half2*>(&x),
                        *reinterpret_cast<__half2*>(&bias));
    __half2 z = __floats2half2_rn(0.f, 0.f);
    __half2 r = __hmax2(v, z);
    return *reinterpret_cast<uint32_t*>(&r);
}
DEV void mbar_init(uint32_t mbar, uint32_t cnt) {
    asm volatile("mbarrier.init.shared.b64 [%0], %1;" :: "r"(mbar), "r"(cnt) : "memory");
}
DEV void mbar_expect(uint32_t mbar, uint32_t bytes) {
    asm volatile("mbarrier.arrive.expect_tx.shared.b64 _, [%0], %1;" :: "r"(mbar), "r"(bytes) : "memory");
}
DEV void mbar_wait(uint32_t mbar, uint32_t parity) {
    asm volatile(
        "{\n\t.reg .pred P;\n\t"
        "LW%=:\n\t"
        "mbarrier.try_wait.parity.acquire.cta.shared::cta.b64 P, [%0], %1, 0x989680;\n\t"
        "@P bra LD%=;\n\t"
        "bra LW%=;\n\t"
        "LD%=:\n\t}"
        :: "r"(mbar), "r"(parity) : "memory");
}
DEV void bulk_g2s(uint32_t dst, const void* src, uint32_t bytes, uint32_t mbar) {
    asm volatile(
        "cp.async.bulk.shared::cta.global.mbarrier::complete_tx::bytes [%0], [%1], %2, [%3];"
        :: "r"(dst), "l"(src), "r"(bytes), "r"(mbar) : "memory");
}
DEV void ldsm4(uint32_t* r, uint32_t addr) {
    asm volatile("ldmatrix.sync.aligned.m8n8.x4.shared.b16 {%0,%1,%2,%3}, [%4];"
        : "=r"(r[0]), "=r"(r[1]), "=r"(r[2]), "=r"(r[3]) : "r"(addr));
}
// f32-accumulate MMA (layer 2)
DEV void mma16816(float* c, const uint32_t* a, uint32_t b0, uint32_t b1) {
    asm volatile(
        "mma.sync.aligned.m16n8k16.row.col.f32.f16.f16.f32 "
        "{%0,%1,%2,%3}, {%4,%5,%6,%7}, {%8,%9}, {%0,%1,%2,%3};"
        : "+f"(c[0]), "+f"(c[1]), "+f"(c[2]), "+f"(c[3])
        : "r"(a[0]), "r"(a[1]), "r"(a[2]), "r"(a[3]), "r"(b0), "r"(b1));
}
// f16-accumulate MMA (layer 1) — D fragment is A-fragment-layout compatible
DEV void mma16816h(uint32_t* c, const uint32_t* a, uint32_t b0, uint32_t b1) {
    asm volatile(
        "mma.sync.aligned.m16n8k16.row.col.f16.f16.f16.f16 "
        "{%0,%1}, {%2,%3,%4,%5}, {%6,%7}, {%0,%1};"
        : "+r"(c[0]), "+r"(c[1])
        : "r"(a[0]), "r"(a[1]), "r"(a[2]), "r"(a[3]), "r"(b0), "r"(b1));
}
DEV void named_bar(int id) {
    asm volatile("bar.sync %0, 128;" :: "r"(id) : "memory");
}
DEV void sts128(uint32_t addr, uint32_t a, uint32_t b, uint32_t c, uint32_t d) {
    asm volatile("st.shared.v4.u32 [%0], {%1, %2, %3, %4};"
        :: "r"(addr), "r"(a), "r"(b), "r"(c), "r"(d) : "memory");
}

// ---------------- globals: per-batch bias + single-launch sync flags ----------------
__device__ float g_cbias[BATCH * 256];
__device__ int   g_done   = 0;
__device__ int   g_passed = 0;

// ---------------- main fused kernel (single launch) ----------------
__global__ void __launch_bounds__(256, 1)
edge_mlp_kernel(const float* __restrict__ nodes,   // [NROWS,128]
                const float* __restrict__ newn,    // [BATCH,128]
                const float* __restrict__ W1,      // [256,256]
                const float* __restrict__ b1,      // [256]
                const float* __restrict__ W2,      // [256,64]
                const float* __restrict__ W3,      // [64]
                const float* __restrict__ b2,      // [64]
                const float* __restrict__ b3,      // [1]
                float* __restrict__ out)           // [NROWS]
{
    extern __shared__ char smem[];
    const uint32_t sb = s2u(smem);
    const int tid  = threadIdx.x;
    const int wid  = tid >> 5;
    const int lane = tid & 31;
    const int l7   = lane & 7;
    const int l3   = lane & 3;
    const int rsel = (lane >> 3) & 1;
    const int usub = lane >> 4;
    const int g    = tid >> 7;          // group 0: warps 0-3; group 1: warps 4-7
    const int gtid = tid & 127;

    float* w3_s = reinterpret_cast<float*>(smem + OFF_W3);
    float* b2_s = reinterpret_cast<float*>(smem + OFF_B2C);
    float* b3_s = reinterpret_cast<float*>(smem + OFF_B3);
    uint32_t* cs_h = reinterpret_cast<uint32_t*>(smem + OFF_CS) + g * 128;
    float* stg  = reinterpret_cast<float*>(smem + OFF_STG);

    const uint32_t sbar = sb + OFF_BAR;

    if (tid == 0) mbar_init(sbar, 1);
    __syncthreads();

    // load 0: tile blockIdx.x, rows [0,128) — issued ASAP, overlaps prologue
    if (tid == 0) {
        mbar_expect(sbar, 65536);
        bulk_g2s(sb + OFF_STG, nodes + (size_t)blockIdx.x * (256 * HID), 65536, sbar);
    }

    if (tid < 64) { w3_s[tid] = W3[tid]; b2_s[tid] = b2[tid]; }
    if (tid == 0) b3_s[0] = b3[0];

    // producer CTAs compute per-batch bias c[b] = b1 + new[b] @ W1[128:256]
    if (blockIdx.x < BATCH) {
        const int n = tid;
        float acc = b1[n];
        const float* nb = newn + (size_t)blockIdx.x * HID;
#pragma unroll 8
        for (int f = 0; f < HID; ++f)
            acc = fmaf(nb[f], W1[(size_t)(HID + f) * 256 + n], acc);
        g_cbias[blockIdx.x * 256 + n] = acc;
        __threadfence();
        __syncthreads();
        if (tid == 0) atomicAdd(&g_done, 1);
    }

    // B1: [n=256][k=128] f16, 256B rows, XOR swizzle. B1[n][k]=W1[k*256+n]
    {
        const int n = tid;
#pragma unroll 4
        for (int kp = 0; kp < 64; ++kp) {
            float a = W1[(size_t)(2 * kp) * 256 + n];
            float b = W1[(size_t)(2 * kp + 1) * 256 + n];
            uint32_t addr = (uint32_t)(n * 256 + (((kp >> 2) ^ (n & 7)) << 4) + (kp & 3) * 4);
            *reinterpret_cast<uint32_t*>(smem + OFF_B1 + addr) = pack2(a, b);
        }
    }
    // B2: [n=64][k=256] f16, 512B rows, same swizzle. B2[n][k]=W2[k*64+n]
    {
#pragma unroll 4
        for (int j = 0; j < 32; ++j) {
            int idx = tid + j * 256;
            int n  = idx & 63;
            int kp = idx >> 6;
            float a = W2[(size_t)(2 * kp) * 64 + n];
            float b = W2[(size_t)(2 * kp + 1) * 64 + n];
            uint32_t addr = (uint32_t)(n * 512 + (((kp >> 2) ^ (n & 7)) << 4) + (kp & 3) * 4);
            *reinterpret_cast<uint32_t*>(smem + OFF_B2 + addr) = pack2(a, b);
        }
    }
    __syncthreads();

    // wait for all bias producers; self-reset flags for graph replay
    if (tid == 0) {
        while (*((volatile int*)&g_done) < BATCH) { }
        if (atomicAdd(&g_passed, 1) == (int)gridDim.x - 1) {
            g_done = 0;
            g_passed = 0;
            __threadfence();
        }
    }
    __syncthreads();
    // after this point: NO full-CTA barriers; the two groups run decoupled.

    // per-warp ldmatrix lane bases
    const uint32_t aBase0 = sb + OFF_A1 + (uint32_t)((wid * 32      + l7 + (rsel << 3)) * 256);
    const uint32_t aBase1 = sb + OFF_A1 + (uint32_t)((wid * 32 + 16 + l7 + (rsel << 3)) * 256);
    const uint32_t b1LaneBase = sb + OFF_B1 + (uint32_t)((l7 + (rsel << 3)) * 256);
    const uint32_t b2LaneBase = sb + OFF_B2 + (uint32_t)((l7 + (rsel << 3)) * 512);
    const uint32_t soff0 = (uint32_t)((usub ^ l7) << 4);

    const int grid = gridDim.x;

    for (int t = blockIdx.x; t < NT2; t += grid) {
        // ---- prefetch per-tile bias into regs BEFORE waiting (hides LDG latency) ----
        const int b = t >> 4;
        const float2 cbv = *reinterpret_cast<const float2*>(&g_cbias[b * 256 + 2 * gtid]);

        // ---- wait my group's staged half ----
        // loads alternate g0,g1,g0,g1,... so each group's loads always complete at
        // the SAME parity: group g waits parity g every iteration (proven in R8).
        mbar_wait(sbar, (uint32_t)g);

        cs_h[gtid] = pack2(cbv.x, cbv.y);

        // ---- convert stage fp32 -> f16 swizzled A1 rows [g*128, g*128+128) ----
#pragma unroll 4
        for (int j = 0; j < 16; ++j) {
            int idx = gtid + j * 128;
            int m   = idx >> 4;
            int u   = idx & 15;
            float4 v0 = reinterpret_cast<const float4*>(stg)[m * 32 + u * 2];
            float4 v1 = reinterpret_cast<const float4*>(stg)[m * 32 + u * 2 + 1];
            uint32_t addr = sb + OFF_A1 +
                (uint32_t)((g * 128 + m) * 256 + ((u ^ (m & 7)) << 4));
            sts128(addr, pack2(v0.x, v0.y), pack2(v0.z, v0.w),
                         pack2(v1.x, v1.y), pack2(v1.z, v1.w));
        }
        named_bar(1 + g);

        // ---- group leader issues the NEXT load (stage buffer now free) ----
        if (gtid == 0) {
            if (g == 0) {
                mbar_expect(sbar, 65536);
                bulk_g2s(sb + OFF_STG, nodes + ((size_t)t * 256 + 128) * HID, 65536, sbar);
            } else if (t + grid < NT2) {
                mbar_expect(sbar, 65536);
                bulk_g2s(sb + OFF_STG, nodes + (size_t)(t + grid) * 256 * HID, 65536, sbar);
            }
        }

        // ---- load A fragments: 32 rows x 128 k -> 2 halves x 8 k-steps ----
        uint32_t areg[2][8][4];
#pragma unroll
        for (int s = 0; s < 8; ++s) {
            ldsm4(areg[0][s], aBase0 + (uint32_t)((((s << 1) + usub) ^ l7) << 4));
            ldsm4(areg[1][s], aBase1 + (uint32_t)((((s << 1) + usub) ^ l7) << 4));
        }

        float c2[2][8][4];
#pragma unroll
        for (int h = 0; h < 2; ++h)
#pragma unroll
            for (int f = 0; f < 8; ++f)
#pragma unroll
                for (int q = 0; q < 4; ++q) c2[h][f][q] = 0.f;

        uint32_t brc0[4];
        ldsm4(brc0, b1LaneBase + soff0);   // pp=0, s=0 (stream 0)

        for (int pp = 0; pp < 8; ++pp) {
            const int p0 = 2 * pp;
            // c1[stream][row-half][4] — f16 accum, doubles as layer-2 A fragment
            uint32_t c1[2][2][4];
#pragma unroll
            for (int pb = 0; pb < 2; ++pb)
#pragma unroll
                for (int h = 0; h < 2; ++h)
#pragma unroll
                    for (int q = 0; q < 4; ++q) c1[pb][h][q] = 0u;

            const uint32_t bB0 = b1LaneBase + (uint32_t)(p0 * 4096);

            // ---- layer 1: 8 k-steps; stream0 pipelined across pp ----
#pragma unroll
            for (int s = 0; s < 8; ++s) {
                const uint32_t soff = (uint32_t)((((s << 1) + usub) ^ l7) << 4);
                uint32_t br1[4];
                ldsm4(br1, bB0 + 4096 + soff);
                mma16816h(&c1[0][0][0], areg[0][s], brc0[0], brc0[2]);
                mma16816h(&c1[0][0][2], areg[0][s], brc0[1], brc0[3]);
                mma16816h(&c1[0][1][0], areg[1][s], brc0[0], brc0[2]);
                mma16816h(&c1[0][1][2], areg[1][s], brc0[1], brc0[3]);
                uint32_t brn0[4];
                ldsm4(brn0, (s < 7)
                        ? bB0 + (uint32_t)(((((s + 1) << 1) + usub) ^ l7) << 4)
                        : bB0 + 8192 + soff0);   // s=0 of next pp (pp=7: dummy in B2 region)
                mma16816h(&c1[1][0][0], areg[0][s], br1[0], br1[2]);
                mma16816h(&c1[1][0][2], areg[0][s], br1[1], br1[3]);
                mma16816h(&c1[1][1][0], areg[1][s], br1[0], br1[2]);
                mma16816h(&c1[1][1][2], areg[1][s], br1[1], br1[3]);
                brc0[0] = brn0[0]; brc0[1] = brn0[1]; brc0[2] = brn0[2]; brc0[3] = brn0[3];
            }

            const uint32_t koffA = (uint32_t)((((p0 << 1) + usub) ^ l7) << 4);
            const uint32_t koffB = (uint32_t)(((((p0 + 1) << 1) + usub) ^ l7) << 4);

            // preload stream-A B2 fragments (latency hidden by epilogue-1 below)
            uint32_t rA0[4], rA1[4], rA2[4], rA3[4];
            uint32_t rB0[4], rB1[4], rB2[4], rB3[4];
            ldsm4(rA0, b2LaneBase + koffA);
            ldsm4(rA1, b2LaneBase + 8192 + koffA);

            // epilogue-1: in-place half2 bias + relu; c1 IS the layer-2 A fragment
            {
                const int cbase = p0 * 8;
                const uint32_t bv0 = cs_h[cbase + l3];
                const uint32_t bv1 = cs_h[cbase + 4 + l3];
                c1[0][0][0] = hadd2_relu(c1[0][0][0], bv0);
                c1[0][0][1] = hadd2_relu(c1[0][0][1], bv0);
                c1[0][0][2] = hadd2_relu(c1[0][0][2], bv1);
                c1[0][0][3] = hadd2_relu(c1[0][0][3], bv1);
                c1[0][1][0] = hadd2_relu(c1[0][1][0], bv0);
                c1[0][1][1] = hadd2_relu(c1[0][1][1], bv0);
                c1[0][1][2] = hadd2_relu(c1[0][1][2], bv1);
                c1[0][1][3] = hadd2_relu(c1[0][1][3], bv1);
                const uint32_t bv2 = cs_h[cbase + 8 + l3];
                const uint32_t bv3 = cs_h[cbase + 12 + l3];
                c1[1][0][0] = hadd2_relu(c1[1][0][0], bv2);
                c1[1][0][1] = hadd2_relu(c1[1][0][1], bv2);
                c1[1][0][2] = hadd2_relu(c1[1][0][2], bv3);
                c1[1][0][3] = hadd2_relu(c1[1][0][3], bv3);
                c1[1][1][0] = hadd2_relu(c1[1][1][0], bv2);
                c1[1][1][1] = hadd2_relu(c1[1][1][1], bv2);
                c1[1][1][2] = hadd2_relu(c1[1][1][2], bv3);
                c1[1][1][3] = hadd2_relu(c1[1][1][3], bv3);
            }

            ldsm4(rA2, b2LaneBase + 16384 + koffA);
            ldsm4(rA3, b2LaneBase + 24576 + koffA);

            // ---- layer 2: all stream-A (k=p0) then all stream-B (k=p0+1) ----
            // per-accumulator order identical to R8 (A then B) -> bit-identical result
            mma16816(c2[0][0], c1[0][0], rA0[0], rA0[2]);
            mma16816(c2[0][1], c1[0][0], rA0[1], rA0[3]);
            mma16816(c2[1][0], c1[0][1], rA0[0], rA0[2]);
            mma16816(c2[1][1], c1[0][1], rA0[1], rA0[3]);
            ldsm4(rB0, b2LaneBase + koffB);
            mma16816(c2[0][2], c1[0][0], rA1[0], rA1[2]);
            mma16816(c2[0][3], c1[0][0], rA1[1], rA1[3]);
            mma16816(c2[1][2], c1[0][1], rA1[0], rA1[2]);
            mma16816(c2[1][3], c1[0][1], rA1[1], rA1[3]);
            ldsm4(rB1, b2LaneBase + 8192 + koffB);
            mma16816(c2[0][4], c1[0][0], rA2[0], rA2[2]);
            mma16816(c2[0][5], c1[0][0], rA2[1], rA2[3]);
            mma16816(c2[1][4], c1[0][1], rA2[0], rA2[2]);
            mma16816(c2[1][5], c1[0][1], rA2[1], rA2[3]);
            ldsm4(rB2, b2LaneBase + 16384 + koffB);
            mma16816(c2[0][6], c1[0][0], rA3[0], rA3[2]);
            mma16816(c2[0][7], c1[0][0], rA3[1], rA3[3]);
            mma16816(c2[1][6], c1[0][1], rA3[0], rA3[2]);
            mma16816(c2[1][7], c1[0][1], rA3[1], rA3[3]);
            ldsm4(rB3, b2LaneBase + 24576 + koffB);
            mma16816(c2[0][0], c1[1][0], rB0[0], rB0[2]);
            mma16816(c2[0][1], c1[1][0], rB0[1], rB0[3]);
            mma16816(c2[1][0], c1[1][1], rB0[0], rB0[2]);
            mma16816(c2[1][1], c1[1][1], rB0[1], rB0[3]);
            mma16816(c2[0][2], c1[1][0], rB1[0], rB1[2]);
            mma16816(c2[0][3], c1[1][0], rB1[1], rB1[3]);
            mma16816(c2[1][2], c1[1][1], rB1[0], rB1[2]);
            mma16816(c2[1][3], c1[1][1], rB1[1], rB1[3]);
            mma16816(c2[0][4], c1[1][0], rB2[0], rB2[2]);
            mma16816(c2[0][5], c1[1][0], rB2[1], rB2[3]);
            mma16816(c2[1][4], c1[1][1], rB2[0], rB2[2]);
            mma16816(c2[1][5], c1[1][1], rB2[1], rB2[3]);
            mma16816(c2[0][6], c1[1][0], rB3[0], rB3[2]);
            mma16816(c2[0][7], c1[1][0], rB3[1], rB3[3]);
            mma16816(c2[1][6], c1[1][1], rB3[0], rB3[2]);
            mma16816(c2[1][7], c1[1][1], rB3[1], rB3[3]);
        }

        // ---- epilogue 2: relu(C2 + b2) . W3 + b3 -> sigmoid -> out ----
        const float bias3 = b3_s[0];
#pragma unroll
        for (int h = 0; h < 2; ++h) {
            float accl = 0.f, acch = 0.f;
#pragma unroll
            for (int f2 = 0; f2 < 8; ++f2) {
                const int col = f2 * 8 + l3 * 2;
                float w0 = w3_s[col], w1 = w3_s[col + 1];
                float bb0 = b2_s[col], bb1 = b2_s[col + 1];
                accl = fmaf(fmaxf(c2[h][f2][0] + bb0, 0.f), w0, accl);
                accl = fmaf(fmaxf(c2[h][f2][1] + bb1, 0.f), w1, accl);
                acch = fmaf(fmaxf(c2[h][f2][2] + bb0, 0.f), w0, acch);
                acch = fmaf(fmaxf(c2[h][f2][3] + bb1, 0.f), w1, acch);
            }
            accl += __shfl_xor_sync(0xffffffffu, accl, 1);
            accl += __shfl_xor_sync(0xffffffffu, accl, 2);
            acch += __shfl_xor_sync(0xffffffffu, acch, 1);
            acch += __shfl_xor_sync(0xffffffffu, acch, 2);
            if (l3 == 0) {
                const int row = t * 256 + wid * 32 + 16 * h + (lane >> 2);
                out[row]     = 1.f / (1.f + __expf(-(accl + bias3)));
                out[row + 8] = 1.f / (1.f + __expf(-(acch + bias3)));
            }
        }

        named_bar(1 + g);   // protect cs_h (and ordering) for the next iteration
    }
}

// ---------------- launch ----------------
extern "C" void kernel_launch(void* const* d_in, const int* in_sizes, int n_in,
                              void* d_out, int out_size) {
    const float* nodes = (const float*)d_in[0];   // [128,4096,128]
    const float* newn  = (const float*)d_in[1];   // [128,1,128]
    const float* W1    = (const float*)d_in[2];   // [256,256]
    const float* b1    = (const float*)d_in[3];   // [256]
    const float* W2    = (const float*)d_in[4];   // [256,64]
    const float* b2    = (const float*)d_in[5];   // [64]
    const float* W3    = (const float*)d_in[6];   // [64,1]
    const float* b3    = (const float*)d_in[7];   // [1]
    float* out = (float*)d_out;

    (void)in_sizes; (void)n_in; (void)out_size;

    cudaFuncSetAttribute(edge_mlp_kernel,
                         cudaFuncAttributeMaxDynamicSharedMemorySize, SMEM_BYTES);

    int nsm = 148;
    cudaDeviceGetAttribute(&nsm, cudaDevAttrMultiProcessorCount, 0);
    if (nsm <= 0) nsm = 148;
    if (nsm > NT2) nsm = NT2;

    edge_mlp_kernel<<<nsm, 256, SMEM_BYTES>>>(nodes, newn, W1, b1, W2, W3, b2, b3, out);
}

// round 15
// speedup vs baseline: 1.0710x; 1.0076x over previous
#include <cuda_runtime.h>
#include <cuda_fp16.h>
#include <cstdint>

#define DEV __device__ __forceinline__

// ---------------- problem constants ----------------
static constexpr int HID    = 128;
static constexpr int BATCH  = 128;
static constexpr int NROWS  = 128 * 4096;     // 524288
static constexpr int NT2    = NROWS / 256;    // 2048 tiles of 256 rows

// ---------------- SMEM layout (byte offsets) ----------------
static constexpr int OFF_BAR  = 0;                  // mbarrier (8B)
static constexpr int OFF_W3   = 64;                 // 64 f32
static constexpr int OFF_B2C  = 320;                // 64 f32
static constexpr int OFF_B3   = 576;                // 1 f32
static constexpr int OFF_CS   = 1024;               // [2][128] half2 bias (1KB)
static constexpr int OFF_A1   = 3072;               // 256 x 128 f16 swizzled (64KB)
static constexpr int OFF_B1   = OFF_A1 + 65536;     // 256n x 128k f16 swizzled (64KB)
static constexpr int OFF_B2   = OFF_B1 + 65536;     // 64n x 256k f16 swizzled (32KB)
static constexpr int OFF_STG  = OFF_B2 + 32768;     // fp32 stage: 128 rows x 128 (64KB)
static constexpr int SMEM_BYTES = OFF_STG + 65536;  // 232448 == opt-in max

// ---------------- helpers ----------------
DEV uint32_t s2u(const void* p) {
    uint32_t a;
    asm("{ .reg .u64 t; cvta.to.shared.u64 t, %1; cvt.u32.u64 %0, t; }" : "=r"(a) : "l"(p));
    return a;
}
DEV uint32_t pack2(float a, float b) {
    __half2 h = __floats2half2_rn(a, b);
    return *reinterpret_cast<uint32_t*>(&h);
}
DEV uint32_t hadd2_relu(uint32_t x, uint32_t bias) {
    __half2 v = __hadd2(*reinterpret_cast<__half2*>(&x),
                        *reinterpret_cast<__half2*>(&bias));
    __half2 z = __floats2half2_rn(0.f, 0.f);
    __half2 r = __hmax2(v, z);
    return *reinterpret_cast<uint32_t*>(&r);
}
DEV void mbar_init(uint32_t mbar, uint32_t cnt) {
    asm volatile("mbarrier.init.shared.b64 [%0], %1;" :: "r"(mbar), "r"(cnt) : "memory");
}
DEV void mbar_expect(uint32_t mbar, uint32_t bytes) {
    asm volatile("mbarrier.arrive.expect_tx.shared.b64 _, [%0], %1;" :: "r"(mbar), "r"(bytes) : "memory");
}
DEV void mbar_wait(uint32_t mbar, uint32_t parity) {
    asm volatile(
        "{\n\t.reg .pred P;\n\t"
        "LW%=:\n\t"
        "mbarrier.try_wait.parity.acquire.cta.shared::cta.b64 P, [%0], %1, 0x989680;\n\t"
        "@P bra LD%=;\n\t"
        "bra LW%=;\n\t"
        "LD%=:\n\t}"
        :: "r"(mbar), "r"(parity) : "memory");
}
DEV void bulk_g2s(uint32_t dst, const void* src, uint32_t bytes, uint32_t mbar) {
    asm volatile(
        "cp.async.bulk.shared::cta.global.mbarrier::complete_tx::bytes [%0], [%1], %2, [%3];"
        :: "r"(dst), "l"(src), "r"(bytes), "r"(mbar) : "memory");
}
DEV void ldsm4(uint32_t* r, uint32_t addr) {
    asm volatile("ldmatrix.sync.aligned.m8n8.x4.shared.b16 {%0,%1,%2,%3}, [%4];"
        : "=r"(r[0]), "=r"(r[1]), "=r"(r[2]), "=r"(r[3]) : "r"(addr));
}
// f32-accumulate MMA (layer 2)
DEV void mma16816(float* c, const uint32_t* a, uint32_t b0, uint32_t b1) {
    asm volatile(
        "mma.sync.aligned.m16n8k16.row.col.f32.f16.f16.f32 "
        "{%0,%1,%2,%3}, {%4,%5,%6,%7}, {%8,%9}, {%0,%1,%2,%3};"
        : "+f"(c[0]), "+f"(c[1]), "+f"(c[2]), "+f"(c[3])
        : "r"(a[0]), "r"(a[1]), "r"(a[2]), "r"(a[3]), "r"(b0), "r"(b1));
}
// f16-accumulate MMA (layer 1) — D fragment is A-fragment-layout compatible
DEV void mma16816h(uint32_t* c, const uint32_t* a, uint32_t b0, uint32_t b1) {
    asm volatile(
        "mma.sync.aligned.m16n8k16.row.col.f16.f16.f16.f16 "
        "{%0,%1}, {%2,%3,%4,%5}, {%6,%7}, {%0,%1};"
        : "+r"(c[0]), "+r"(c[1])
        : "r"(a[0]), "r"(a[1]), "r"(a[2]), "r"(a[3]), "r"(b0), "r"(b1));
}
DEV void bar_sync128(int id) {
    asm volatile("bar.sync %0, 128;" :: "r"(id) : "memory");
}
DEV void bar_arrive128(int id) {
    asm volatile("bar.arrive %0, 128;" :: "r"(id) : "memory");
}
DEV void sts128(uint32_t addr, uint32_t a, uint32_t b, uint32_t c, uint32_t d) {
    asm volatile("st.shared.v4.u32 [%0], {%1, %2, %3, %4};"
        :: "r"(addr), "r"(a), "r"(b), "r"(c), "r"(d) : "memory");
}

// ---------------- globals: per-batch bias + single-launch sync flags ----------------
__device__ float g_cbias[BATCH * 256];
__device__ int   g_done   = 0;
__device__ int   g_passed = 0;

// ---------------- main fused kernel (single launch) ----------------
__global__ void __launch_bounds__(256, 1)
edge_mlp_kernel(const float* __restrict__ nodes,   // [NROWS,128]
                const float* __restrict__ newn,    // [BATCH,128]
                const float* __restrict__ W1,      // [256,256]
                const float* __restrict__ b1,      // [256]
                const float* __restrict__ W2,      // [256,64]
                const float* __restrict__ W3,      // [64]
                const float* __restrict__ b2,      // [64]
                const float* __restrict__ b3,      // [1]
                float* __restrict__ out)           // [NROWS]
{
    extern __shared__ char smem[];
    const uint32_t sb = s2u(smem);
    const int tid  = threadIdx.x;
    const int wid  = tid >> 5;
    const int lane = tid & 31;
    const int l7   = lane & 7;
    const int l3   = lane & 3;
    const int rsel = (lane >> 3) & 1;
    const int usub = lane >> 4;
    const int g    = tid >> 7;          // group 0: warps 0-3; group 1: warps 4-7
    const int gtid = tid & 127;
    const int gwid = wid & 3;           // warp within group (0 = leader)

    float* w3_s = reinterpret_cast<float*>(smem + OFF_W3);
    float* b2_s = reinterpret_cast<float*>(smem + OFF_B2C);
    float* b3_s = reinterpret_cast<float*>(smem + OFF_B3);
    uint32_t* cs_h = reinterpret_cast<uint32_t*>(smem + OFF_CS) + g * 128;
    float* stg  = reinterpret_cast<float*>(smem + OFF_STG);

    const uint32_t sbar = sb + OFF_BAR;

    if (tid == 0) mbar_init(sbar, 1);
    __syncthreads();

    // load 0: tile blockIdx.x, rows [0,128) — issued ASAP, overlaps prologue
    if (tid == 0) {
        mbar_expect(sbar, 65536);
        bulk_g2s(sb + OFF_STG, nodes + (size_t)blockIdx.x * (256 * HID), 65536, sbar);
    }

    if (tid < 64) { w3_s[tid] = W3[tid]; b2_s[tid] = b2[tid]; }
    if (tid == 0) b3_s[0] = b3[0];

    // producer CTAs compute per-batch bias c[b] = b1 + new[b] @ W1[128:256]
    if (blockIdx.x < BATCH) {
        const int n = tid;
        float acc = b1[n];
        const float* nb = newn + (size_t)blockIdx.x * HID;
#pragma unroll 8
        for (int f = 0; f < HID; ++f)
            acc = fmaf(nb[f], W1[(size_t)(HID + f) * 256 + n], acc);
        g_cbias[blockIdx.x * 256 + n] = acc;
        __threadfence();
        __syncthreads();
        if (tid == 0) atomicAdd(&g_done, 1);
    }

    // B1: [n=256][k=128] f16, 256B rows, XOR swizzle. B1[n][k]=W1[k*256+n]
    {
        const int n = tid;
#pragma unroll 4
        for (int kp = 0; kp < 64; ++kp) {
            float a = W1[(size_t)(2 * kp) * 256 + n];
            float b = W1[(size_t)(2 * kp + 1) * 256 + n];
            uint32_t addr = (uint32_t)(n * 256 + (((kp >> 2) ^ (n & 7)) << 4) + (kp & 3) * 4);
            *reinterpret_cast<uint32_t*>(smem + OFF_B1 + addr) = pack2(a, b);
        }
    }
    // B2: [n=64][k=256] f16, 512B rows, same swizzle. B2[n][k]=W2[k*64+n]
    {
#pragma unroll 4
        for (int j = 0; j < 32; ++j) {
            int idx = tid + j * 256;
            int n  = idx & 63;
            int kp = idx >> 6;
            float a = W2[(size_t)(2 * kp) * 64 + n];
            float b = W2[(size_t)(2 * kp + 1) * 64 + n];
            uint32_t addr = (uint32_t)(n * 512 + (((kp >> 2) ^ (n & 7)) << 4) + (kp & 3) * 4);
            *reinterpret_cast<uint32_t*>(smem + OFF_B2 + addr) = pack2(a, b);
        }
    }
    __syncthreads();

    // wait for all bias producers; self-reset flags for graph replay
    if (tid == 0) {
        while (*((volatile int*)&g_done) < BATCH) { }
        if (atomicAdd(&g_passed, 1) == (int)gridDim.x - 1) {
            g_done = 0;
            g_passed = 0;
            __threadfence();
        }
    }
    __syncthreads();
    // after this point: NO full-CTA barriers; the two groups run decoupled.

    // per-warp ldmatrix lane bases
    const uint32_t aBase0 = sb + OFF_A1 + (uint32_t)((wid * 32      + l7 + (rsel << 3)) * 256);
    const uint32_t aBase1 = sb + OFF_A1 + (uint32_t)((wid * 32 + 16 + l7 + (rsel << 3)) * 256);
    const uint32_t b1LaneBase = sb + OFF_B1 + (uint32_t)((l7 + (rsel << 3)) * 256);
    const uint32_t b2LaneBase = sb + OFF_B2 + (uint32_t)((l7 + (rsel << 3)) * 512);
    const uint32_t soff0 = (uint32_t)((usub ^ l7) << 4);

    const int grid = gridDim.x;

    for (int t = blockIdx.x; t < NT2; t += grid) {
        // ---- prefetch per-tile bias into regs BEFORE waiting (hides LDG latency) ----
        const int b = t >> 4;
        const float2 cbv = *reinterpret_cast<const float2*>(&g_cbias[b * 256 + 2 * gtid]);

        // ---- wait my group's staged half (parity == g: loads alternate g0,g1,...) ----
        mbar_wait(sbar, (uint32_t)g);

        cs_h[gtid] = pack2(cbv.x, cbv.y);

        // ---- convert OWN 32 rows fp32 -> f16 swizzled A1 (warp-private) ----
        // warp owns local rows [gwid*32, gwid*32+32); ldmatrix below reads only these.
#pragma unroll 4
        for (int j = 0; j < 16; ++j) {
            int idx  = lane + j * 32;                // 0..511
            int m    = gwid * 32 + (idx >> 4);       // local row in [gwid*32, +32)
            int u    = idx & 15;                     // 16B unit 0..15
            float4 v0 = reinterpret_cast<const float4*>(stg)[m * 32 + u * 2];
            float4 v1 = reinterpret_cast<const float4*>(stg)[m * 32 + u * 2 + 1];
            uint32_t addr = sb + OFF_A1 +
                (uint32_t)((g * 128 + m) * 256 + ((u ^ (m & 7)) << 4));
            sts128(addr, pack2(v0.x, v0.y), pack2(v0.z, v0.w),
                         pack2(v1.x, v1.y), pack2(v1.z, v1.w));
        }
        __syncwarp();   // make own-warp STS visible cross-lane for ldmatrix

        // ---- signal "my stage reads done": non-leaders don't block ----
        if (gwid != 0) {
            bar_arrive128(1 + g);
        } else {
            bar_sync128(1 + g);          // leader waits for all 4 warps
            if (lane == 0) {             // then issues the NEXT load (stage free)
                if (g == 0) {
                    mbar_expect(sbar, 65536);
                    bulk_g2s(sb + OFF_STG, nodes + ((size_t)t * 256 + 128) * HID, 65536, sbar);
                } else if (t + grid < NT2) {
                    mbar_expect(sbar, 65536);
                    bulk_g2s(sb + OFF_STG, nodes + (size_t)(t + grid) * 256 * HID, 65536, sbar);
                }
            }
        }

        // ---- load A fragments (own rows only — no barrier needed) ----
        uint32_t areg[2][8][4];
#pragma unroll
        for (int s = 0; s < 8; ++s) {
            ldsm4(areg[0][s], aBase0 + (uint32_t)((((s << 1) + usub) ^ l7) << 4));
            ldsm4(areg[1][s], aBase1 + (uint32_t)((((s << 1) + usub) ^ l7) << 4));
        }

        float c2[2][8][4];
#pragma unroll
        for (int h = 0; h < 2; ++h)
#pragma unroll
            for (int f = 0; f < 8; ++f)
#pragma unroll
                for (int q = 0; q < 4; ++q) c2[h][f][q] = 0.f;

        uint32_t brc0[4];
        ldsm4(brc0, b1LaneBase + soff0);   // pp=0, s=0 (stream 0)

        for (int pp = 0; pp < 8; ++pp) {
            const int p0 = 2 * pp;
            // c1[stream][row-half][4] — f16 accum, doubles as layer-2 A fragment
            uint32_t c1[2][2][4];
#pragma unroll
            for (int pb = 0; pb < 2; ++pb)
#pragma unroll
                for (int h = 0; h < 2; ++h)
#pragma unroll
                    for (int q = 0; q < 4; ++q) c1[pb][h][q] = 0u;

            const uint32_t bB0 = b1LaneBase + (uint32_t)(p0 * 4096);

            // ---- layer 1: 8 k-steps; stream0 pipelined across pp (R8 exact) ----
#pragma unroll
            for (int s = 0; s < 8; ++s) {
                const uint32_t soff = (uint32_t)((((s << 1) + usub) ^ l7) << 4);
                uint32_t br1[4];
                ldsm4(br1, bB0 + 4096 + soff);
                mma16816h(&c1[0][0][0], areg[0][s], brc0[0], brc0[2]);
                mma16816h(&c1[0][0][2], areg[0][s], brc0[1], brc0[3]);
                mma16816h(&c1[0][1][0], areg[1][s], brc0[0], brc0[2]);
                mma16816h(&c1[0][1][2], areg[1][s], brc0[1], brc0[3]);
                uint32_t brn0[4];
                ldsm4(brn0, (s < 7)
                        ? bB0 + (uint32_t)(((((s + 1) << 1) + usub) ^ l7) << 4)
                        : bB0 + 8192 + soff0);   // s=0 of next pp (pp=7: dummy in B2 region)
                mma16816h(&c1[1][0][0], areg[0][s], br1[0], br1[2]);
                mma16816h(&c1[1][0][2], areg[0][s], br1[1], br1[3]);
                mma16816h(&c1[1][1][0], areg[1][s], br1[0], br1[2]);
                mma16816h(&c1[1][1][2], areg[1][s], br1[1], br1[3]);
                brc0[0] = brn0[0]; brc0[1] = brn0[1]; brc0[2] = brn0[2]; brc0[3] = brn0[3];
            }

            const uint32_t koffA = (uint32_t)((((p0 << 1) + usub) ^ l7) << 4);
            const uint32_t koffB = (uint32_t)(((((p0 + 1) << 1) + usub) ^ l7) << 4);

            // prefetch first layer-2 B fragment (hidden by bias+relu below) — R8 exact
            uint32_t br2a[4];
            ldsm4(br2a, b2LaneBase + koffA);

            // epilogue-1: in-place half2 bias + relu; c1 IS the layer-2 A fragment
            {
                const int cbase = p0 * 8;
                const uint32_t bv0 = cs_h[cbase + l3];
                const uint32_t bv1 = cs_h[cbase + 4 + l3];
                c1[0][0][0] = hadd2_relu(c1[0][0][0], bv0);
                c1[0][0][1] = hadd2_relu(c1[0][0][1], bv0);
                c1[0][0][2] = hadd2_relu(c1[0][0][2], bv1);
                c1[0][0][3] = hadd2_relu(c1[0][0][3], bv1);
                c1[0][1][0] = hadd2_relu(c1[0][1][0], bv0);
                c1[0][1][1] = hadd2_relu(c1[0][1][1], bv0);
                c1[0][1][2] = hadd2_relu(c1[0][1][2], bv1);
                c1[0][1][3] = hadd2_relu(c1[0][1][3], bv1);
                const uint32_t bv2 = cs_h[cbase + 8 + l3];
                const uint32_t bv3 = cs_h[cbase + 12 + l3];
                c1[1][0][0] = hadd2_relu(c1[1][0][0], bv2);
                c1[1][0][1] = hadd2_relu(c1[1][0][1], bv2);
                c1[1][0][2] = hadd2_relu(c1[1][0][2], bv3);
                c1[1][0][3] = hadd2_relu(c1[1][0][3], bv3);
                c1[1][1][0] = hadd2_relu(c1[1][1][0], bv2);
                c1[1][1][1] = hadd2_relu(c1[1][1][1], bv2);
                c1[1][1][2] = hadd2_relu(c1[1][1][2], bv3);
                c1[1][1][3] = hadd2_relu(c1[1][1][3], bv3);
            }

            // ---- layer 2: k-steps p0 (stream A) then p0+1 (stream B); R8 exact ----
#pragma unroll
            for (int p2 = 0; p2 < 4; ++p2) {
                const uint32_t rowB = (uint32_t)(p2 * 8192);
                uint32_t br2b[4];
                ldsm4(br2b, b2LaneBase + rowB + koffB);
                uint32_t br2an[4];
                if (p2 < 3)
                    ldsm4(br2an, b2LaneBase + (uint32_t)((p2 + 1) * 8192) + koffA);
                // stream A (k = p0): c1[0][h]
                mma16816(c2[0][2 * p2],     c1[0][0], br2a[0], br2a[2]);
                mma16816(c2[0][2 * p2 + 1], c1[0][0], br2a[1], br2a[3]);
                mma16816(c2[1][2 * p2],     c1[0][1], br2a[0], br2a[2]);
                mma16816(c2[1][2 * p2 + 1], c1[0][1], br2a[1], br2a[3]);
                // stream B (k = p0+1): c1[1][h]
                mma16816(c2[0][2 * p2],     c1[1][0], br2b[0], br2b[2]);
                mma16816(c2[0][2 * p2 + 1], c1[1][0], br2b[1], br2b[3]);
                mma16816(c2[1][2 * p2],     c1[1][1], br2b[0], br2b[2]);
                mma16816(c2[1][2 * p2 + 1], c1[1][1], br2b[1], br2b[3]);
                if (p2 < 3) {
                    br2a[0] = br2an[0]; br2a[1] = br2an[1]; br2a[2] = br2an[2]; br2a[3] = br2an[3];
                }
            }
        }

        // ---- epilogue 2: relu(C2 + b2) . W3 + b3 -> sigmoid -> out ----
        const float bias3 = b3_s[0];
#pragma unroll
        for (int h = 0; h < 2; ++h) {
            float accl = 0.f, acch = 0.f;
#pragma unroll
            for (int f2 = 0; f2 < 8; ++f2) {
                const int col = f2 * 8 + l3 * 2;
                float w0 = w3_s[col], w1 = w3_s[col + 1];
                float bb0 = b2_s[col], bb1 = b2_s[col + 1];
                accl = fmaf(fmaxf(c2[h][f2][0] + bb0, 0.f), w0, accl);
                accl = fmaf(fmaxf(c2[h][f2][1] + bb1, 0.f), w1, accl);
                acch = fmaf(fmaxf(c2[h][f2][2] + bb0, 0.f), w0, acch);
                acch = fmaf(fmaxf(c2[h][f2][3] + bb1, 0.f), w1, acch);
            }
            accl += __shfl_xor_sync(0xffffffffu, accl, 1);
            accl += __shfl_xor_sync(0xffffffffu, accl, 2);
            acch += __shfl_xor_sync(0xffffffffu, acch, 1);
            acch += __shfl_xor_sync(0xffffffffu, acch, 2);
            if (l3 == 0) {
                const int row = t * 256 + wid * 32 + 16 * h + (lane >> 2);
                out[row]     = 1.f / (1.f + __expf(-(accl + bias3)));
                out[row + 8] = 1.f / (1.f + __expf(-(acch + bias3)));
            }
        }

        bar_sync128(3 + g);   // trailing: protect cs_h rewrite next iteration
    }
}

// ---------------- launch ----------------
extern "C" void kernel_launch(void* const* d_in, const int* in_sizes, int n_in,
                              void* d_out, int out_size) {
    const float* nodes = (const float*)d_in[0];   // [128,4096,128]
    const float* newn  = (const float*)d_in[1];   // [128,1,128]
    const float* W1    = (const float*)d_in[2];   // [256,256]
    const float* b1    = (const float*)d_in[3];   // [256]
    const float* W2    = (const float*)d_in[4];   // [256,64]
    const float* b2    = (const float*)d_in[5];   // [64]
    const float* W3    = (const float*)d_in[6];   // [64,1]
    const float* b3    = (const float*)d_in[7];   // [1]
    float* out = (float*)d_out;

    (void)in_sizes; (void)n_in; (void)out_size;

    cudaFuncSetAttribute(edge_mlp_kernel,
                         cudaFuncAttributeMaxDynamicSharedMemorySize, SMEM_BYTES);

    int nsm = 148;
    cudaDeviceGetAttribute(&nsm, cudaDevAttrMultiProcessorCount, 0);
    if (nsm <= 0) nsm = 148;
    if (nsm > NT2) nsm = NT2;

    edge_mlp_kernel<<<nsm, 256, SMEM_BYTES>>>(nodes, newn, W1, b1, W2, W3, b2, b3, out);
}

// round 17
// speedup vs baseline: 1.0781x; 1.0066x over previous
#include <cuda_runtime.h>
#include <cuda_fp16.h>
#include <cstdint>

#define DEV __device__ __forceinline__

// ---------------- problem constants ----------------
static constexpr int HID    = 128;
static constexpr int BATCH  = 128;
static constexpr int NROWS  = 128 * 4096;     // 524288
static constexpr int NT2    = NROWS / 256;    // 2048 tiles of 256 rows

// ---------------- SMEM layout (byte offsets) ----------------
static constexpr int OFF_BAR  = 0;                  // mbarrier (8B)
static constexpr int OFF_W3   = 64;                 // 64 f32
static constexpr int OFF_B2C  = 320;                // 64 f32
static constexpr int OFF_B3   = 576;                // 1 f32
static constexpr int OFF_A1   = 3072;               // 256 x 128 f16 swizzled (64KB)
static constexpr int OFF_B1   = OFF_A1 + 65536;     // 256n x 128k f16 swizzled (64KB)
static constexpr int OFF_B2   = OFF_B1 + 65536;     // 64n x 256k f16 swizzled (32KB)
static constexpr int OFF_STG  = OFF_B2 + 32768;     // fp32 stage: 128 rows x 128 (64KB)
static constexpr int SMEM_BYTES = OFF_STG + 65536;  // 232448 == opt-in max

// ---------------- helpers ----------------
DEV uint32_t s2u(const void* p) {
    uint32_t a;
    asm("{ .reg .u64 t; cvta.to.shared.u64 t, %1; cvt.u32.u64 %0, t; }" : "=r"(a) : "l"(p));
    return a;
}
DEV uint32_t pack2(float a, float b) {
    __half2 h = __floats2half2_rn(a, b);
    return *reinterpret_cast<uint32_t*>(&h);
}
DEV uint32_t hadd2_relu(uint32_t x, uint32_t bias) {
    __half2 v = __hadd2(*reinterpret_cast<__half2*>(&x),
                        *reinterpret_cast<__half2*>(&bias));
    __half2 z = __floats2half2_rn(0.f, 0.f);
    __half2 r = __hmax2(v, z);
    return *reinterpret_cast<uint32_t*>(&r);
}
DEV void mbar_init(uint32_t mbar, uint32_t cnt) {
    asm volatile("mbarrier.init.shared.b64 [%0], %1;" :: "r"(mbar), "r"(cnt) : "memory");
}
DEV void mbar_expect(uint32_t mbar, uint32_t bytes) {
    asm volatile("mbarrier.arrive.expect_tx.shared.b64 _, [%0], %1;" :: "r"(mbar), "r"(bytes) : "memory");
}
DEV void mbar_wait(uint32_t mbar, uint32_t parity) {
    asm volatile(
        "{\n\t.reg .pred P;\n\t"
        "LW%=:\n\t"
        "mbarrier.try_wait.parity.acquire.cta.shared::cta.b64 P, [%0], %1, 0x989680;\n\t"
        "@P bra LD%=;\n\t"
        "bra LW%=;\n\t"
        "LD%=:\n\t}"
        :: "r"(mbar), "r"(parity) : "memory");
}
DEV void bulk_g2s(uint32_t dst, const void* src, uint32_t bytes, uint32_t mbar) {
    asm volatile(
        "cp.async.bulk.shared::cta.global.mbarrier::complete_tx::bytes [%0], [%1], %2, [%3];"
        :: "r"(dst), "l"(src), "r"(bytes), "r"(mbar) : "memory");
}
DEV void ldsm4(uint32_t* r, uint32_t addr) {
    asm volatile("ldmatrix.sync.aligned.m8n8.x4.shared.b16 {%0,%1,%2,%3}, [%4];"
        : "=r"(r[0]), "=r"(r[1]), "=r"(r[2]), "=r"(r[3]) : "r"(addr));
}
// f32-accumulate MMA (layer 2)
DEV void mma16816(float* c, const uint32_t* a, uint32_t b0, uint32_t b1) {
    asm volatile(
        "mma.sync.aligned.m16n8k16.row.col.f32.f16.f16.f32 "
        "{%0,%1,%2,%3}, {%4,%5,%6,%7}, {%8,%9}, {%0,%1,%2,%3};"
        : "+f"(c[0]), "+f"(c[1]), "+f"(c[2]), "+f"(c[3])
        : "r"(a[0]), "r"(a[1]), "r"(a[2]), "r"(a[3]), "r"(b0), "r"(b1));
}
// f16-accumulate MMA (layer 1) — D fragment is A-fragment-layout compatible
DEV void mma16816h(uint32_t* c, const uint32_t* a, uint32_t b0, uint32_t b1) {
    asm volatile(
        "mma.sync.aligned.m16n8k16.row.col.f16.f16.f16.f16 "
        "{%0,%1}, {%2,%3,%4,%5}, {%6,%7}, {%0,%1};"
        : "+r"(c[0]), "+r"(c[1])
        : "r"(a[0]), "r"(a[1]), "r"(a[2]), "r"(a[3]), "r"(b0), "r"(b1));
}
DEV void bar_sync128(int id) {
    asm volatile("bar.sync %0, 128;" :: "r"(id) : "memory");
}
DEV void bar_arrive128(int id) {
    asm volatile("bar.arrive %0, 128;" :: "r"(id) : "memory");
}
DEV void sts128(uint32_t addr, uint32_t a, uint32_t b, uint32_t c, uint32_t d) {
    asm volatile("st.shared.v4.u32 [%0], {%1, %2, %3, %4};"
        :: "r"(addr), "r"(a), "r"(b), "r"(c), "r"(d) : "memory");
}

// ---------------- globals: packed per-batch bias + single-launch sync flags ----------------
__device__ uint32_t g_cbias_h2[BATCH * 128];   // half2-packed c[b] = b1 + new[b] @ W1[128:256]
__device__ int      g_done   = 0;
__device__ int      g_passed = 0;

// ---------------- main fused kernel (single launch) ----------------
__global__ void __launch_bounds__(256, 1)
edge_mlp_kernel(const float* __restrict__ nodes,   // [NROWS,128]
                const float* __restrict__ newn,    // [BATCH,128]
                const float* __restrict__ W1,      // [256,256]
                const float* __restrict__ b1,      // [256]
                const float* __restrict__ W2,      // [256,64]
                const float* __restrict__ W3,      // [64]
                const float* __restrict__ b2,      // [64]
                const float* __restrict__ b3,      // [1]
                float* __restrict__ out)           // [NROWS]
{
    extern __shared__ char smem[];
    const uint32_t sb = s2u(smem);
    const int tid  = threadIdx.x;
    const int wid  = tid >> 5;
    const int lane = tid & 31;
    const int l7   = lane & 7;
    const int l3   = lane & 3;
    const int rsel = (lane >> 3) & 1;
    const int usub = lane >> 4;
    const int g    = tid >> 7;          // group 0: warps 0-3; group 1: warps 4-7
    const int gwid = wid & 3;           // warp within group (0 = leader)

    float* w3_s = reinterpret_cast<float*>(smem + OFF_W3);
    float* b2_s = reinterpret_cast<float*>(smem + OFF_B2C);
    float* b3_s = reinterpret_cast<float*>(smem + OFF_B3);
    float* stg  = reinterpret_cast<float*>(smem + OFF_STG);

    const uint32_t sbar = sb + OFF_BAR;
    const int grid = gridDim.x;
    const int bx = blockIdx.x;

    if (tid == 0) mbar_init(sbar, 1);
    __syncthreads();

    // load 0: tile bx, rows [0,128) — issued ASAP, overlaps prologue
    if (tid == 0) {
        mbar_expect(sbar, 65536);
        bulk_g2s(sb + OFF_STG, nodes + (size_t)bx * (256 * HID), 65536, sbar);
    }

    if (tid < 64) { w3_s[tid] = W3[tid]; b2_s[tid] = b2[tid]; }
    if (tid == 0) b3_s[0] = b3[0];

    // producer CTAs compute per-batch bias c[b] = b1 + new[b] @ W1[128:256],
    // packed to half2 (same pack2 rounding as before -> bit-identical epilogue)
    if (bx < BATCH) {
        float* scr = reinterpret_cast<float*>(smem + OFF_A1);   // scratch, pre-convert
        const int n = tid;
        float acc = b1[n];
        const float* nb = newn + (size_t)bx * HID;
#pragma unroll 8
        for (int f = 0; f < HID; ++f)
            acc = fmaf(nb[f], W1[(size_t)(HID + f) * 256 + n], acc);
        scr[n] = acc;
        __syncthreads();
        if (tid < 128)
            g_cbias_h2[bx * 128 + tid] = pack2(scr[2 * tid], scr[2 * tid + 1]);
        __threadfence();
        __syncthreads();
        if (tid == 0) atomicAdd(&g_done, 1);
    }

    // B1: [n=256][k=128] f16, 256B rows, XOR swizzle. B1[n][k]=W1[k*256+n]
    {
        const int n = tid;
#pragma unroll 4
        for (int kp = 0; kp < 64; ++kp) {
            float a = W1[(size_t)(2 * kp) * 256 + n];
            float b = W1[(size_t)(2 * kp + 1) * 256 + n];
            uint32_t addr = (uint32_t)(n * 256 + (((kp >> 2) ^ (n & 7)) << 4) + (kp & 3) * 4);
            *reinterpret_cast<uint32_t*>(smem + OFF_B1 + addr) = pack2(a, b);
        }
    }
    // B2: [n=64][k=256] f16, 512B rows, same swizzle. B2[n][k]=W2[k*64+n]
    {
#pragma unroll 4
        for (int j = 0; j < 32; ++j) {
            int idx = tid + j * 256;
            int n  = idx & 63;
            int kp = idx >> 6;
            float a = W2[(size_t)(2 * kp) * 64 + n];
            float b = W2[(size_t)(2 * kp + 1) * 64 + n];
            uint32_t addr = (uint32_t)(n * 512 + (((kp >> 2) ^ (n & 7)) << 4) + (kp & 3) * 4);
            *reinterpret_cast<uint32_t*>(smem + OFF_B2 + addr) = pack2(a, b);
        }
    }
    __syncthreads();

    // wait for all bias producers; self-reset flags for graph replay
    if (tid == 0) {
        while (*((volatile int*)&g_done) < BATCH) { }
        if (atomicAdd(&g_passed, 1) == (int)gridDim.x - 1) {
            g_done = 0;
            g_passed = 0;
            __threadfence();
        }
    }
    __syncthreads();
    // after this point: groups decoupled; within a group warps drift up to one tile
    // (only coupling: arrive/sync barrier gating the stage-buffer reuse).

    // per-warp ldmatrix lane bases
    const uint32_t aBase0 = sb + OFF_A1 + (uint32_t)((wid * 32      + l7 + (rsel << 3)) * 256);
    const uint32_t aBase1 = sb + OFF_A1 + (uint32_t)((wid * 32 + 16 + l7 + (rsel << 3)) * 256);
    const uint32_t b1LaneBase = sb + OFF_B1 + (uint32_t)((l7 + (rsel << 3)) * 256);
    const uint32_t b2LaneBase = sb + OFF_B2 + (uint32_t)((l7 + (rsel << 3)) * 512);
    const uint32_t soff0 = (uint32_t)((usub ^ l7) << 4);

    for (int t = bx; t < NT2; t += grid) {
        // ---- wait my group's staged half (parity == g; loads strictly alternate) ----
        mbar_wait(sbar, (uint32_t)g);

        // ---- convert OWN 32 rows fp32 -> f16 swizzled A1 (warp-private) ----
#pragma unroll 4
        for (int j = 0; j < 16; ++j) {
            int idx  = lane + j * 32;                // 0..511
            int m    = gwid * 32 + (idx >> 4);       // local row in [gwid*32, +32)
            int u    = idx & 15;                     // 16B unit 0..15
            float4 v0 = reinterpret_cast<const float4*>(stg)[m * 32 + u * 2];
            float4 v1 = reinterpret_cast<const float4*>(stg)[m * 32 + u * 2 + 1];
            uint32_t addr = sb + OFF_A1 +
                (uint32_t)((g * 128 + m) * 256 + ((u ^ (m & 7)) << 4));
            sts128(addr, pack2(v0.x, v0.y), pack2(v0.z, v0.w),
                         pack2(v1.x, v1.y), pack2(v1.z, v1.w));
        }
        __syncwarp();   // own-warp STS visible cross-lane for ldmatrix

        // ---- signal stage-read-done: non-leaders don't block ----
        if (gwid != 0) {
            bar_arrive128(1 + g);
        } else {
            bar_sync128(1 + g);          // leader waits all 4 warps done with stage
            if (lane == 0) {             // then issues the NEXT load (stage free)
                if (g == 0) {
                    mbar_expect(sbar, 65536);
                    bulk_g2s(sb + OFF_STG, nodes + ((size_t)t * 256 + 128) * HID, 65536, sbar);
                } else if (t + grid < NT2) {
                    mbar_expect(sbar, 65536);
                    bulk_g2s(sb + OFF_STG, nodes + (size_t)(t + grid) * 256 * HID, 65536, sbar);
                }
            }
        }

        // ---- load A fragments (own rows only — no barrier needed) ----
        uint32_t areg[2][8][4];
#pragma unroll
        for (int s = 0; s < 8; ++s) {
            ldsm4(areg[0][s], aBase0 + (uint32_t)((((s << 1) + usub) ^ l7) << 4));
            ldsm4(areg[1][s], aBase1 + (uint32_t)((((s << 1) + usub) ^ l7) << 4));
        }

        float c2[2][8][4];
#pragma unroll
        for (int h = 0; h < 2; ++h)
#pragma unroll
            for (int f = 0; f < 8; ++f)
#pragma unroll
                for (int q = 0; q < 4; ++q) c2[h][f][q] = 0.f;

        const uint32_t* gbias = g_cbias_h2 + (t >> 4) * 128;

        uint32_t brc0[4];
        ldsm4(brc0, b1LaneBase + soff0);   // pp=0, s=0 (stream 0)

        for (int pp = 0; pp < 8; ++pp) {
            const int p0 = 2 * pp;

            // bias prefetch via LDG (L1/L2-hot; consumed ~64 MMAs later)
            const uint32_t bv0 = __ldg(gbias + p0 * 8 + l3);
            const uint32_t bv1 = __ldg(gbias + p0 * 8 + 4 + l3);
            const uint32_t bv2 = __ldg(gbias + p0 * 8 + 8 + l3);
            const uint32_t bv3 = __ldg(gbias + p0 * 8 + 12 + l3);

            // c1[stream][row-half][4] — f16 accum, doubles as layer-2 A fragment
            uint32_t c1[2][2][4];
#pragma unroll
            for (int pb = 0; pb < 2; ++pb)
#pragma unroll
                for (int h = 0; h < 2; ++h)
#pragma unroll
                    for (int q = 0; q < 4; ++q) c1[pb][h][q] = 0u;

            const uint32_t bB0 = b1LaneBase + (uint32_t)(p0 * 4096);

            // ---- layer 1: 8 k-steps; stream0 pipelined across pp (R8 exact) ----
#pragma unroll
            for (int s = 0; s < 8; ++s) {
                const uint32_t soff = (uint32_t)((((s << 1) + usub) ^ l7) << 4);
                uint32_t br1[4];
                ldsm4(br1, bB0 + 4096 + soff);
                mma16816h(&c1[0][0][0], areg[0][s], brc0[0], brc0[2]);
                mma16816h(&c1[0][0][2], areg[0][s], brc0[1], brc0[3]);
                mma16816h(&c1[0][1][0], areg[1][s], brc0[0], brc0[2]);
                mma16816h(&c1[0][1][2], areg[1][s], brc0[1], brc0[3]);
                uint32_t brn0[4];
                ldsm4(brn0, (s < 7)
                        ? bB0 + (uint32_t)(((((s + 1) << 1) + usub) ^ l7) << 4)
                        : bB0 + 8192 + soff0);   // s=0 of next pp (pp=7: dummy in B2 region)
                mma16816h(&c1[1][0][0], areg[0][s], br1[0], br1[2]);
                mma16816h(&c1[1][0][2], areg[0][s], br1[1], br1[3]);
                mma16816h(&c1[1][1][0], areg[1][s], br1[0], br1[2]);
                mma16816h(&c1[1][1][2], areg[1][s], br1[1], br1[3]);
                brc0[0] = brn0[0]; brc0[1] = brn0[1]; brc0[2] = brn0[2]; brc0[3] = brn0[3];
            }

            const uint32_t koffA = (uint32_t)((((p0 << 1) + usub) ^ l7) << 4);
            const uint32_t koffB = (uint32_t)(((((p0 + 1) << 1) + usub) ^ l7) << 4);

            // prefetch first layer-2 B fragment (hidden by bias+relu below) — R8 exact
            uint32_t br2a[4];
            ldsm4(br2a, b2LaneBase + koffA);

            // epilogue-1: in-place half2 bias + relu; c1 IS the layer-2 A fragment
            {
                c1[0][0][0] = hadd2_relu(c1[0][0][0], bv0);
                c1[0][0][1] = hadd2_relu(c1[0][0][1], bv0);
                c1[0][0][2] = hadd2_relu(c1[0][0][2], bv1);
                c1[0][0][3] = hadd2_relu(c1[0][0][3], bv1);
                c1[0][1][0] = hadd2_relu(c1[0][1][0], bv0);
                c1[0][1][1] = hadd2_relu(c1[0][1][1], bv0);
                c1[0][1][2] = hadd2_relu(c1[0][1][2], bv1);
                c1[0][1][3] = hadd2_relu(c1[0][1][3], bv1);
                c1[1][0][0] = hadd2_relu(c1[1][0][0], bv2);
                c1[1][0][1] = hadd2_relu(c1[1][0][1], bv2);
                c1[1][0][2] = hadd2_relu(c1[1][0][2], bv3);
                c1[1][0][3] = hadd2_relu(c1[1][0][3], bv3);
                c1[1][1][0] = hadd2_relu(c1[1][1][0], bv2);
                c1[1][1][1] = hadd2_relu(c1[1][1][1], bv2);
                c1[1][1][2] = hadd2_relu(c1[1][1][2], bv3);
                c1[1][1][3] = hadd2_relu(c1[1][1][3], bv3);
            }

            // ---- layer 2: k-steps p0 (stream A) then p0+1 (stream B); R8 exact ----
#pragma unroll
            for (int p2 = 0; p2 < 4; ++p2) {
                const uint32_t rowB = (uint32_t)(p2 * 8192);
                uint32_t br2b[4];
                ldsm4(br2b, b2LaneBase + rowB + koffB);
                uint32_t br2an[4];
                if (p2 < 3)
                    ldsm4(br2an, b2LaneBase + (uint32_t)((p2 + 1) * 8192) + koffA);
                // stream A (k = p0): c1[0][h]
                mma16816(c2[0][2 * p2],     c1[0][0], br2a[0], br2a[2]);
                mma16816(c2[0][2 * p2 + 1], c1[0][0], br2a[1], br2a[3]);
                mma16816(c2[1][2 * p2],     c1[0][1], br2a[0], br2a[2]);
                mma16816(c2[1][2 * p2 + 1], c1[0][1], br2a[1], br2a[3]);
                // stream B (k = p0+1): c1[1][h]
                mma16816(c2[0][2 * p2],     c1[1][0], br2b[0], br2b[2]);
                mma16816(c2[0][2 * p2 + 1], c1[1][0], br2b[1], br2b[3]);
                mma16816(c2[1][2 * p2],     c1[1][1], br2b[0], br2b[2]);
                mma16816(c2[1][2 * p2 + 1], c1[1][1], br2b[1], br2b[3]);
                if (p2 < 3) {
                    br2a[0] = br2an[0]; br2a[1] = br2an[1]; br2a[2] = br2an[2]; br2a[3] = br2an[3];
                }
            }
        }

        // ---- epilogue 2: relu(C2 + b2) . W3 + b3 -> sigmoid -> out ----
        const float bias3 = b3_s[0];
#pragma unroll
        for (int h = 0; h < 2; ++h) {
            float accl = 0.f, acch = 0.f;
#pragma unroll
            for (int f2 = 0; f2 < 8; ++f2) {
                const int col = f2 * 8 + l3 * 2;
                float w0 = w3_s[col], w1 = w3_s[col + 1];
                float bb0 = b2_s[col], bb1 = b2_s[col + 1];
                accl = fmaf(fmaxf(c2[h][f2][0] + bb0, 0.f), w0, accl);
                accl = fmaf(fmaxf(c2[h][f2][1] + bb1, 0.f), w1, accl);
                acch = fmaf(fmaxf(c2[h][f2][2] + bb0, 0.f), w0, acch);
                acch = fmaf(fmaxf(c2[h][f2][3] + bb1, 0.f), w1, acch);
            }
            accl += __shfl_xor_sync(0xffffffffu, accl, 1);
            accl += __shfl_xor_sync(0xffffffffu, accl, 2);
            acch += __shfl_xor_sync(0xffffffffu, acch, 1);
            acch += __shfl_xor_sync(0xffffffffu, acch, 2);
            if (l3 == 0) {
                const int row = t * 256 + wid * 32 + 16 * h + (lane >> 2);
                out[row]     = 1.f / (1.f + __expf(-(accl + bias3)));
                out[row + 8] = 1.f / (1.f + __expf(-(acch + bias3)));
            }
        }
        // NO trailing barrier: all per-tile smem state is warp-private (A1 rows,
        // areg) or gated (stage via barrier 1+g); bias comes from global.
    }
}

// ---------------- launch ----------------
extern "C" void kernel_launch(void* const* d_in, const int* in_sizes, int n_in,
                              void* d_out, int out_size) {
    const float* nodes = (const float*)d_in[0];   // [128,4096,128]
    const float* newn  = (const float*)d_in[1];   // [128,1,128]
    const float* W1    = (const float*)d_in[2];   // [256,256]
    const float* b1    = (const float*)d_in[3];   // [256]
    const float* W2    = (const float*)d_in[4];   // [256,64]
    const float* b2    = (const float*)d_in[5];   // [64]
    const float* W3    = (const float*)d_in[6];   // [64,1]
    const float* b3    = (const float*)d_in[7];   // [1]
    float* out = (float*)d_out;

    (void)in_sizes; (void)n_in; (void)out_size;

    cudaFuncSetAttribute(edge_mlp_kernel,
                         cudaFuncAttributeMaxDynamicSharedMemorySize, SMEM_BYTES);

    int nsm = 148;
    cudaDeviceGetAttribute(&nsm, cudaDevAttrMultiProcessorCount, 0);
    if (nsm <= 0) nsm = 148;
    if (nsm > NT2) nsm = NT2;

    edge_mlp_kernel<<<nsm, 256, SMEM_BYTES>>>(nodes, newn, W1, b1, W2, W3, b2, b3, out);
}